// round 9
// baseline (speedup 1.0000x reference)
#include <cuda_runtime.h>
#include <cuda_bf16.h>
#include <cstdint>
#include <math.h>

#define ATT_SCALE 0.0625f
typedef uint32_t u32;

// ---------------- SMEM byte offsets ------------------------------------------
#define WCHUNK  24576              // one staged W chunk: hi(12288) + lo(12288)
#define S_WBUF  0                  // 3 x WCHUNK ring
#define S_AHI   73728              // 64 x 264 bf16
#define S_ALO   107520
#define S_AFF   141312             // 256 fp32
#define S_F1B   142336
#define S_F2W   143360
#define S_OSUM  144384             // 64 x 4 fp32
#define S_TOTAL 145408
#define A_STR   264                // bf16 per A row (pad: conflict-free ldmatrix)

// ---------------- device scratch ---------------------------------------------
__device__ float g_enc1[65536], g_enc2[65536];
__device__ float g_affa[65536], g_affv[65536];
__device__ float g_Xa[65536],   g_Xv[65536];
__device__ float g_park[1024 * 16384];         // fc1 branch-A partials (per CTA)
// 6 weights x 16 k-chunks x 24576 B (bf16 hi/lo, pre-padded staging layout)
__device__ uint4 g_wsp[6 * 16 * 1536];

// ---------------- small helpers ----------------------------------------------
__device__ __forceinline__ u32 smem_u32(const void* p) {
    u32 a;
    asm("{ .reg .u64 t; cvta.to.shared.u64 t, %1; cvt.u32.u64 %0, t; }" : "=r"(a) : "l"(p));
    return a;
}
__device__ __forceinline__ void ldsm4(u32 addr, u32* d) {
    asm volatile("ldmatrix.sync.aligned.m8n8.x4.shared.b16 {%0,%1,%2,%3}, [%4];"
        : "=r"(d[0]), "=r"(d[1]), "=r"(d[2]), "=r"(d[3]) : "r"(addr));
}
__device__ __forceinline__ void mma_bf16(float* c, const u32* a, const u32* b) {
    asm volatile("mma.sync.aligned.m16n8k16.row.col.f32.bf16.bf16.f32 "
        "{%0,%1,%2,%3}, {%4,%5,%6,%7}, {%8,%9}, {%0,%1,%2,%3};"
        : "+f"(c[0]), "+f"(c[1]), "+f"(c[2]), "+f"(c[3])
        : "r"(a[0]), "r"(a[1]), "r"(a[2]), "r"(a[3]), "r"(b[0]), "r"(b[1]));
}
__device__ __forceinline__ void split2(float v0, float v1, u32& rh, u32& rl) {
    __nv_bfloat16 h0 = __float2bfloat16(v0), h1 = __float2bfloat16(v1);
    __nv_bfloat16 l0 = __float2bfloat16(v0 - __bfloat162float(h0));
    __nv_bfloat16 l1 = __float2bfloat16(v1 - __bfloat162float(h1));
    rh = (u32)__bfloat16_as_ushort(h0) | ((u32)__bfloat16_as_ushort(h1) << 16);
    rl = (u32)__bfloat16_as_ushort(l0) | ((u32)__bfloat16_as_ushort(l1) << 16);
}
__device__ __forceinline__ float ftanh(float x) {
    float t = __expf(fminf(2.0f * x, 80.0f));
    return __fdividef(t - 1.0f, t + 1.0f);
}
#define CP_ASYNC16(dst, src) \
    asm volatile("cp.async.cg.shared.global [%0], [%1], 16;" :: "r"(dst), "l"(src))
#define CP_COMMIT() asm volatile("cp.async.commit_group;" ::: "memory")
#define CP_WAIT1()  asm volatile("cp.async.wait_group 1;" ::: "memory")
#define CP_WAIT0()  asm volatile("cp.async.wait_group 0;" ::: "memory")

// ---------------- prep GEMMs (SIMT fp32, known-correct) -----------------------
__device__ __forceinline__ void small_gemm(const float* __restrict__ A,
                                           const float* __restrict__ W,
                                           const float* __restrict__ bias,
                                           float* __restrict__ C, int K)
{
    __shared__ float As[32][17];
    __shared__ float Ws[64][17];
    const int i0 = blockIdx.x * 32, j0 = blockIdx.y * 64;
    const int tid = threadIdx.x;
    const int tx = tid & 15, ty = tid >> 4;
    const int ar = tid >> 2, ak = (tid & 3) * 4;
    float acc[2][4] = {};
    for (int k0 = 0; k0 < K; k0 += 16) {
        float4 av = make_float4(0.f, 0.f, 0.f, 0.f);
        if (tid < 128) av = *(const float4*)(A + (size_t)(i0 + ar) * K + k0 + ak);
        float4 wv = *(const float4*)(W + (size_t)(j0 + ar) * K + k0 + ak);
        __syncthreads();
        if (tid < 128) {
            As[ar][ak] = av.x; As[ar][ak+1] = av.y; As[ar][ak+2] = av.z; As[ar][ak+3] = av.w;
        }
        Ws[ar][ak] = wv.x; Ws[ar][ak+1] = wv.y; Ws[ar][ak+2] = wv.z; Ws[ar][ak+3] = wv.w;
        __syncthreads();
        #pragma unroll
        for (int kk = 0; kk < 16; kk++) {
            float a0 = As[ty*2][kk], a1 = As[ty*2+1][kk];
            float b0 = Ws[tx*4][kk], b1 = Ws[tx*4+1][kk];
            float b2 = Ws[tx*4+2][kk], b3 = Ws[tx*4+3][kk];
            acc[0][0] = fmaf(a0,b0,acc[0][0]); acc[0][1] = fmaf(a0,b1,acc[0][1]);
            acc[0][2] = fmaf(a0,b2,acc[0][2]); acc[0][3] = fmaf(a0,b3,acc[0][3]);
            acc[1][0] = fmaf(a1,b0,acc[1][0]); acc[1][1] = fmaf(a1,b1,acc[1][1]);
            acc[1][2] = fmaf(a1,b2,acc[1][2]); acc[1][3] = fmaf(a1,b3,acc[1][3]);
        }
    }
    #pragma unroll
    for (int u = 0; u < 2; u++)
        #pragma unroll
        for (int v = 0; v < 4; v++) {
            int j = j0 + tx*4 + v;
            float x = acc[u][v];
            if (bias) x += bias[j];
            C[(size_t)(i0 + ty*2 + u) * 256 + j] = x;
        }
}

__global__ void pre_enc_kernel(const float* __restrict__ f1, const float* __restrict__ f2,
                               const float* __restrict__ w1, const float* __restrict__ b1,
                               const float* __restrict__ w2, const float* __restrict__ b2)
{
    if (blockIdx.z == 0) small_gemm(f1, w1, b1, g_enc1, 768);
    else                 small_gemm(f2, w2, b2, g_enc2, 768);
}

__global__ void pre_aff_kernel(const float* __restrict__ affa, const float* __restrict__ affv,
                               const float* __restrict__ wa,   const float* __restrict__ wv)
{
    int z = blockIdx.z;
    const float* A = (z == 0 || z == 2) ? g_enc1 : g_enc2;
    const float* W = (z == 0) ? affa : (z == 1) ? affv : (z == 2) ? wa : wv;
    float*       C = (z == 0) ? g_affa : (z == 1) ? g_affv : (z == 2) ? g_Xa : g_Xv;
    small_gemm(A, W, nullptr, C, 256);
}

// ---------------- weight split: fp32 -> bf16 hi/lo staging image --------------
__global__ void split_kernel(const float* __restrict__ wca, const float* __restrict__ wcv,
                             const float* __restrict__ wha, const float* __restrict__ whv,
                             const float* __restrict__ fc1w)
{
    int w = blockIdx.x, c = blockIdx.y, j = threadIdx.x;
    const float* src; int stride = 256, co = 0;
    switch (w) {
        case 0: src = wca; break;
        case 1: src = wha; break;
        case 2: src = fc1w; stride = 512; break;
        case 3: src = wcv; break;
        case 4: src = whv; break;
        default: src = fc1w; stride = 512; co = 256; break;
    }
    const float* rp = src + (size_t)j * stride + co + c * 16;
    uint8_t* dst = (uint8_t*)g_wsp + (size_t)(w * 16 + c) * WCHUNK;
    #pragma unroll
    for (int p = 0; p < 8; p++) {
        float f0 = rp[2*p], f1 = rp[2*p + 1];
        u32 rh, rl; split2(f0, f1, rh, rl);
        *(u32*)(dst + j*48 + p*4)         = rh;
        *(u32*)(dst + 12288 + j*48 + p*4) = rl;
    }
}

// ---------------- tensor-core mainloop ---------------------------------------
// CTA tile M=64 x N=256. Warp w: rows [(w&1)*32,+32), cols [(w>>1)*64,+64).
__device__ __forceinline__ void copy_chunk(const char* wsrc, u32 sb, int c, int tid) {
    const char* src = wsrc + (size_t)c * WCHUNK + tid * 96;
    u32 dst = sb + S_WBUF + (u32)(c % 3) * WCHUNK + (u32)(tid * 96);
    #pragma unroll
    for (int q = 0; q < 6; q++) CP_ASYNC16(dst + q*16, src + q*16);
    CP_COMMIT();
}

__device__ __forceinline__ void run_gemm(const char* __restrict__ wsrc, u32 sb,
                                         int tid, int lane, int r0, int c0,
                                         float acc[2][8][4])
{
    #pragma unroll
    for (int mt = 0; mt < 2; mt++)
        #pragma unroll
        for (int nt = 0; nt < 8; nt++)
            #pragma unroll
            for (int q = 0; q < 4; q++) acc[mt][nt][q] = 0.f;

    const int g = lane >> 3, r = lane & 7;
    const int arow = r0 + (g & 1)*8 + r;
    const int jo   = c0 + (g >> 1)*8 + r;
    const int ko   = (g & 1)*8;

    copy_chunk(wsrc, sb, 0, tid);
    copy_chunk(wsrc, sb, 1, tid);

    for (int c = 0; c < 16; c++) {
        if (c < 15) { CP_WAIT1(); } else { CP_WAIT0(); }
        __syncthreads();
        u32 bufb = sb + S_WBUF + (u32)(c % 3) * WCHUNK;
        int akof = c*16 + (g >> 1)*8;

        u32 ah[2][4], al[2][4];
        #pragma unroll
        for (int mt = 0; mt < 2; mt++) {
            u32 ao = sb + S_AHI + (u32)(((arow + mt*16) * A_STR + akof) * 2);
            ldsm4(ao, ah[mt]);
            ldsm4(ao + (S_ALO - S_AHI), al[mt]);
        }
        #pragma unroll
        for (int np = 0; np < 4; np++) {
            u32 bo = bufb + (u32)((jo + np*16) * 48 + ko * 2);
            u32 th[4], tl[4];
            ldsm4(bo, th);
            ldsm4(bo + 12288, tl);
            #pragma unroll
            for (int mt = 0; mt < 2; mt++) {
                mma_bf16(acc[mt][np*2], ah[mt], th);
                mma_bf16(acc[mt][np*2], al[mt], th);
                mma_bf16(acc[mt][np*2], ah[mt], tl);
                mma_bf16(acc[mt][np*2+1], ah[mt], th + 2);
                mma_bf16(acc[mt][np*2+1], al[mt], th + 2);
                mma_bf16(acc[mt][np*2+1], ah[mt], tl + 2);
            }
        }
        if (c + 2 < 16) copy_chunk(wsrc, sb, c + 2, tid);
    }
    __syncthreads();   // all warps done reading A before epilogue overwrites it
}

// ---------------- fused kernel -----------------------------------------------
__global__ void __launch_bounds__(256, 1)
mma_fused(const float* __restrict__ fc1b, const float* __restrict__ fc2w,
          const float* __restrict__ fc2b, float* __restrict__ out)
{
    extern __shared__ char sm[];
    u32 sb = smem_u32(sm);
    const int tid = threadIdx.x, lane = tid & 31, w = tid >> 5;
    const int b = blockIdx.y, i0 = blockIdx.x * 64;
    const int r0 = (w & 1) * 32, c0 = (w >> 1) * 64;
    const int qr = lane >> 2, qc = (lane & 3) * 2;
    float* park = g_park + (size_t)(blockIdx.y * 4 + blockIdx.x) * 16384;

    ((float*)(sm + S_F1B))[tid] = fc1b[tid];
    ((float*)(sm + S_F2W))[tid] = fc2w[tid];

    float acc[2][8][4];

    for (int br = 0; br < 2; br++) {
        const float* genc = br ? g_enc2 : g_enc1;
        const float* gaff = br ? g_affv : g_affa;
        const float* gX   = br ? g_Xv   : g_Xa;
        const char*  wb   = (const char*)(g_wsp + (size_t)(br * 3) * 16 * 1536);

        __syncthreads();
        ((float*)(sm + S_AFF))[tid] = gaff[b*256 + tid];
        __syncthreads();

        // ---- attn tile -> A hi/lo (rank-1 outer product) ----
        {
            int row = tid >> 2, cb = (tid & 3) * 64;
            float ev = genc[b*256 + i0 + row] * ATT_SCALE;
            const float* aff = (const float*)(sm + S_AFF);
            #pragma unroll 4
            for (int p = 0; p < 32; p++) {
                int col = cb + 2*p;
                float v0 = ftanh(ev * aff[col]), v1 = ftanh(ev * aff[col + 1]);
                u32 rh, rl; split2(v0, v1, rh, rl);
                u32 off = (u32)((row * A_STR + col) * 2);
                *(u32*)(sm + S_AHI + off) = rh;
                *(u32*)(sm + S_ALO + off) = rl;
            }
        }

        // ---- GEMM1: D = attn @ Wc^T ; A = relu(D + X) ----
        run_gemm(wb, sb, tid, lane, r0, c0, acc);
        #pragma unroll
        for (int mt = 0; mt < 2; mt++)
            #pragma unroll
            for (int rs = 0; rs < 2; rs++) {
                int row = r0 + mt*16 + rs*8 + qr;
                #pragma unroll
                for (int nt = 0; nt < 8; nt++) {
                    int col = c0 + nt*8 + qc;
                    float2 xv = *(const float2*)(gX + (size_t)(i0 + row)*256 + col);
                    float v0 = fmaxf(acc[mt][nt][rs*2]   + xv.x, 0.f);
                    float v1 = fmaxf(acc[mt][nt][rs*2+1] + xv.y, 0.f);
                    u32 rh, rl; split2(v0, v1, rh, rl);
                    u32 off = (u32)((row * A_STR + col) * 2);
                    *(u32*)(sm + S_AHI + off) = rh;
                    *(u32*)(sm + S_ALO + off) = rl;
                }
            }

        // ---- GEMM2: D = H @ Wh^T ; A = D + enc ----
        run_gemm(wb + (size_t)16 * WCHUNK, sb, tid, lane, r0, c0, acc);
        #pragma unroll
        for (int mt = 0; mt < 2; mt++)
            #pragma unroll
            for (int rs = 0; rs < 2; rs++) {
                int row = r0 + mt*16 + rs*8 + qr;
                #pragma unroll
                for (int nt = 0; nt < 8; nt++) {
                    int col = c0 + nt*8 + qc;
                    float2 ev2 = *(const float2*)(genc + (size_t)(i0 + row)*256 + col);
                    float v0 = acc[mt][nt][rs*2]   + ev2.x;
                    float v1 = acc[mt][nt][rs*2+1] + ev2.y;
                    u32 rh, rl; split2(v0, v1, rh, rl);
                    u32 off = (u32)((row * A_STR + col) * 2);
                    *(u32*)(sm + S_AHI + off) = rh;
                    *(u32*)(sm + S_ALO + off) = rl;
                }
            }

        // ---- GEMM3: D = attn_enc @ fc1_half^T ----
        run_gemm(wb + (size_t)32 * WCHUNK, sb, tid, lane, r0, c0, acc);
        if (br == 0) {
            #pragma unroll
            for (int mt = 0; mt < 2; mt++)
                #pragma unroll
                for (int rs = 0; rs < 2; rs++) {
                    int row = r0 + mt*16 + rs*8 + qr;
                    #pragma unroll
                    for (int nt = 0; nt < 8; nt++) {
                        int col = c0 + nt*8 + qc;
                        *(float2*)(park + row*256 + col) =
                            make_float2(acc[mt][nt][rs*2], acc[mt][nt][rs*2+1]);
                    }
                }
        } else {
            const float* f1bs = (const float*)(sm + S_F1B);
            const float* f2ws = (const float*)(sm + S_F2W);
            #pragma unroll
            for (int mt = 0; mt < 2; mt++)
                #pragma unroll
                for (int rs = 0; rs < 2; rs++) {
                    int row = r0 + mt*16 + rs*8 + qr;
                    float s = 0.f;
                    #pragma unroll
                    for (int nt = 0; nt < 8; nt++) {
                        int col = c0 + nt*8 + qc;
                        float2 pk = *(const float2*)(park + row*256 + col);
                        float h0 = fmaxf(acc[mt][nt][rs*2]   + pk.x + f1bs[col],     0.f);
                        float h1 = fmaxf(acc[mt][nt][rs*2+1] + pk.y + f1bs[col + 1], 0.f);
                        s = fmaf(h0, f2ws[col], s);
                        s = fmaf(h1, f2ws[col + 1], s);
                    }
                    s += __shfl_xor_sync(0xffffffffu, s, 1);
                    s += __shfl_xor_sync(0xffffffffu, s, 2);
                    if ((lane & 3) == 0)
                        ((float*)(sm + S_OSUM))[row*4 + (w >> 1)] = s;
                }
            __syncthreads();
            if (tid < 64) {
                const float* os = (const float*)(sm + S_OSUM);
                out[b*256 + i0 + tid] =
                    os[tid*4] + os[tid*4+1] + os[tid*4+2] + os[tid*4+3] + fc2b[0];
            }
        }
        __syncthreads();
    }
}

// ---------------- launch -----------------------------------------------------
extern "C" void kernel_launch(void* const* d_in, const int* in_sizes, int n_in,
                              void* d_out, int out_size)
{
    (void)in_sizes; (void)n_in; (void)out_size;
    const float* f1     = (const float*)d_in[0];
    const float* f2     = (const float*)d_in[1];
    const float* enc1_w = (const float*)d_in[2];
    const float* enc1_b = (const float*)d_in[3];
    const float* enc2_w = (const float*)d_in[4];
    const float* enc2_b = (const float*)d_in[5];
    const float* affa_w = (const float*)d_in[6];
    const float* affv_w = (const float*)d_in[7];
    const float* wa_w   = (const float*)d_in[8];
    const float* wv_w   = (const float*)d_in[9];
    const float* wca_w  = (const float*)d_in[10];
    const float* wcv_w  = (const float*)d_in[11];
    const float* wha_w  = (const float*)d_in[12];
    const float* whv_w  = (const float*)d_in[13];
    const float* fc1_w  = (const float*)d_in[14];
    const float* fc1_b  = (const float*)d_in[15];
    const float* fc2_w  = (const float*)d_in[16];
    const float* fc2_b  = (const float*)d_in[17];
    float* out = (float*)d_out;

    cudaFuncSetAttribute(mma_fused, cudaFuncAttributeMaxDynamicSharedMemorySize, S_TOTAL);

    split_kernel<<<dim3(6, 16), 256>>>(wca_w, wcv_w, wha_w, whv_w, fc1_w);
    pre_enc_kernel<<<dim3(8, 4, 2), 256>>>(f1, f2, enc1_w, enc1_b, enc2_w, enc2_b);
    pre_aff_kernel<<<dim3(8, 4, 4), 256>>>(affa_w, affv_w, wa_w, wv_w);
    mma_fused<<<dim3(4, 256), 256, S_TOTAL>>>(fc1_b, fc2_w, fc2_b, out);
}

// round 10
// speedup vs baseline: 1.9041x; 1.9041x over previous
#include <cuda_runtime.h>
#include <cuda_bf16.h>
#include <cstdint>
#include <math.h>

#define ATT_SCALE 0.0625f
typedef uint32_t u32;

// ---------------- SMEM byte offsets ------------------------------------------
#define S_AHI   0                  // 64 x 264 bf16
#define S_ALO   33792
#define S_PARK  67584              // 64 x 260 fp32
#define S_AFF   134144             // 256 fp32
#define S_F1B   135168
#define S_F2W   136192
#define S_OSUM  137216             // 64 x 4 fp32
#define S_TOTAL 138240
#define A_STR   264                // bf16 per A row (pad: conflict-free ldmatrix)

// ---------------- device scratch ---------------------------------------------
__device__ float g_enc1[65536], g_enc2[65536];
__device__ float g_affa[65536], g_affv[65536];
__device__ float g_Xa[65536],   g_Xv[65536];
// 6 weights x 16 chunks x 16 colgroups x (hi 32 + lo 32) uint4, fragment order
__device__ uint4 g_wfrag[6 * 16384];

// ---------------- small helpers ----------------------------------------------
__device__ __forceinline__ u32 smem_u32(const void* p) {
    u32 a;
    asm("{ .reg .u64 t; cvta.to.shared.u64 t, %1; cvt.u32.u64 %0, t; }" : "=r"(a) : "l"(p));
    return a;
}
__device__ __forceinline__ void ldsm4(u32 addr, u32* d) {
    asm volatile("ldmatrix.sync.aligned.m8n8.x4.shared.b16 {%0,%1,%2,%3}, [%4];"
        : "=r"(d[0]), "=r"(d[1]), "=r"(d[2]), "=r"(d[3]) : "r"(addr));
}
__device__ __forceinline__ void mma_bf16(float* c, const u32* a, const u32* b) {
    asm volatile("mma.sync.aligned.m16n8k16.row.col.f32.bf16.bf16.f32 "
        "{%0,%1,%2,%3}, {%4,%5,%6,%7}, {%8,%9}, {%0,%1,%2,%3};"
        : "+f"(c[0]), "+f"(c[1]), "+f"(c[2]), "+f"(c[3])
        : "r"(a[0]), "r"(a[1]), "r"(a[2]), "r"(a[3]), "r"(b[0]), "r"(b[1]));
}
__device__ __forceinline__ void split2(float v0, float v1, u32& rh, u32& rl) {
    __nv_bfloat16 h0 = __float2bfloat16(v0), h1 = __float2bfloat16(v1);
    __nv_bfloat16 l0 = __float2bfloat16(v0 - __bfloat162float(h0));
    __nv_bfloat16 l1 = __float2bfloat16(v1 - __bfloat162float(h1));
    rh = (u32)__bfloat16_as_ushort(h0) | ((u32)__bfloat16_as_ushort(h1) << 16);
    rl = (u32)__bfloat16_as_ushort(l0) | ((u32)__bfloat16_as_ushort(l1) << 16);
}
__device__ __forceinline__ float ftanh(float x) {
    float t = __expf(fminf(2.0f * x, 80.0f));
    return __fdividef(t - 1.0f, t + 1.0f);
}

// ---------------- prep GEMMs (SIMT fp32, known-correct) -----------------------
__device__ __forceinline__ void small_gemm(const float* __restrict__ A,
                                           const float* __restrict__ W,
                                           const float* __restrict__ bias,
                                           float* __restrict__ C, int K)
{
    __shared__ float As[32][17];
    __shared__ float Ws[64][17];
    const int i0 = blockIdx.x * 32, j0 = blockIdx.y * 64;
    const int tid = threadIdx.x;
    const int tx = tid & 15, ty = tid >> 4;
    const int ar = tid >> 2, ak = (tid & 3) * 4;
    float acc[2][4] = {};
    for (int k0 = 0; k0 < K; k0 += 16) {
        float4 av = make_float4(0.f, 0.f, 0.f, 0.f);
        if (tid < 128) av = *(const float4*)(A + (size_t)(i0 + ar) * K + k0 + ak);
        float4 wv = *(const float4*)(W + (size_t)(j0 + ar) * K + k0 + ak);
        __syncthreads();
        if (tid < 128) {
            As[ar][ak] = av.x; As[ar][ak+1] = av.y; As[ar][ak+2] = av.z; As[ar][ak+3] = av.w;
        }
        Ws[ar][ak] = wv.x; Ws[ar][ak+1] = wv.y; Ws[ar][ak+2] = wv.z; Ws[ar][ak+3] = wv.w;
        __syncthreads();
        #pragma unroll
        for (int kk = 0; kk < 16; kk++) {
            float a0 = As[ty*2][kk], a1 = As[ty*2+1][kk];
            float b0 = Ws[tx*4][kk], b1 = Ws[tx*4+1][kk];
            float b2 = Ws[tx*4+2][kk], b3 = Ws[tx*4+3][kk];
            acc[0][0] = fmaf(a0,b0,acc[0][0]); acc[0][1] = fmaf(a0,b1,acc[0][1]);
            acc[0][2] = fmaf(a0,b2,acc[0][2]); acc[0][3] = fmaf(a0,b3,acc[0][3]);
            acc[1][0] = fmaf(a1,b0,acc[1][0]); acc[1][1] = fmaf(a1,b1,acc[1][1]);
            acc[1][2] = fmaf(a1,b2,acc[1][2]); acc[1][3] = fmaf(a1,b3,acc[1][3]);
        }
    }
    #pragma unroll
    for (int u = 0; u < 2; u++)
        #pragma unroll
        for (int v = 0; v < 4; v++) {
            int j = j0 + tx*4 + v;
            float x = acc[u][v];
            if (bias) x += bias[j];
            C[(size_t)(i0 + ty*2 + u) * 256 + j] = x;
        }
}

__global__ void pre_enc_kernel(const float* __restrict__ f1, const float* __restrict__ f2,
                               const float* __restrict__ w1, const float* __restrict__ b1,
                               const float* __restrict__ w2, const float* __restrict__ b2)
{
    if (blockIdx.z == 0) small_gemm(f1, w1, b1, g_enc1, 768);
    else                 small_gemm(f2, w2, b2, g_enc2, 768);
}

__global__ void pre_aff_kernel(const float* __restrict__ affa, const float* __restrict__ affv,
                               const float* __restrict__ wa,   const float* __restrict__ wv)
{
    int z = blockIdx.z;
    const float* A = (z == 0 || z == 2) ? g_enc1 : g_enc2;
    const float* W = (z == 0) ? affa : (z == 1) ? affv : (z == 2) ? wa : wv;
    float*       C = (z == 0) ? g_affa : (z == 1) ? g_affv : (z == 2) ? g_Xa : g_Xv;
    small_gemm(A, W, nullptr, C, 256);
}

// ---------------- weight split: fp32 -> bf16 hi/lo FRAGMENT layout ------------
// For (w, chunk c, colgroup jc): 512B hi block + 512B lo block. Lane l's uint4 =
// mma B frag th[0..3]: {n=jc*16+l/4, k=c*16+(l%4)*2}, {n, k+8}, {n+8, k}, {n+8, k+8}.
__global__ void split_kernel(const float* __restrict__ wca, const float* __restrict__ wcv,
                             const float* __restrict__ wha, const float* __restrict__ whv,
                             const float* __restrict__ fc1w)
{
    int w = blockIdx.x, c = blockIdx.y;
    int jc = threadIdx.x >> 5, lane = threadIdx.x & 31;
    const float* src; int stride = 256, co = 0;
    switch (w) {
        case 0: src = wca; break;
        case 1: src = wha; break;
        case 2: src = fc1w; stride = 512; break;
        case 3: src = wcv; break;
        case 4: src = whv; break;
        default: src = fc1w; stride = 512; co = 256; break;
    }
    int n0 = jc * 16 + (lane >> 2);
    int k0 = c * 16 + (lane & 3) * 2;
    const float* r0 = src + (size_t)n0 * stride + co;
    const float* r1 = src + (size_t)(n0 + 8) * stride + co;
    uint4 hv, lv;
    split2(r0[k0],     r0[k0 + 1], hv.x, lv.x);
    split2(r0[k0 + 8], r0[k0 + 9], hv.y, lv.y);
    split2(r1[k0],     r1[k0 + 1], hv.z, lv.z);
    split2(r1[k0 + 8], r1[k0 + 9], hv.w, lv.w);
    uint4* dst = g_wfrag + ((size_t)(w * 16 + c) * 16 + jc) * 64 + lane;
    dst[0]  = hv;
    dst[32] = lv;
}

// ---------------- tensor-core mainloop ---------------------------------------
__device__ __forceinline__ void lda(u32 sb, int arow, int akof, u32 ah[2][4], u32 al[2][4]) {
    #pragma unroll
    for (int mt = 0; mt < 2; mt++) {
        u32 ao = sb + S_AHI + (u32)(((arow + mt*16) * A_STR + akof) * 2);
        ldsm4(ao, ah[mt]);
        ldsm4(ao + (S_ALO - S_AHI), al[mt]);
    }
}
__device__ __forceinline__ void mma_group(float acc[2][8][4], u32 ah[2][4], u32 al[2][4],
                                          uint4 bh[4], uint4 bl[4]) {
    #pragma unroll
    for (int np = 0; np < 4; np++) {
        const u32* th = (const u32*)&bh[np];
        const u32* tl = (const u32*)&bl[np];
        #pragma unroll
        for (int mt = 0; mt < 2; mt++) {
            mma_bf16(acc[mt][np*2],   ah[mt], th);
            mma_bf16(acc[mt][np*2],   al[mt], th);
            mma_bf16(acc[mt][np*2],   ah[mt], tl);
            mma_bf16(acc[mt][np*2+1], ah[mt], th + 2);
            mma_bf16(acc[mt][np*2+1], al[mt], th + 2);
            mma_bf16(acc[mt][np*2+1], ah[mt], tl + 2);
        }
    }
}
#define LOADB(bh, bl, cc) do { \
    _Pragma("unroll") \
    for (int np = 0; np < 4; np++) { \
        const uint4* p = wf + ((size_t)(cc) * 16 + cg4 + np) * 64 + lane; \
        bh[np] = __ldg(p); bl[np] = __ldg(p + 32); \
    } \
} while (0)

// C tile: rows [r0,+32) of the CTA's 64, cols [cg*64,+64). No barriers inside
// the k-loop — B comes straight from GMEM, A is read-only SMEM.
__device__ __forceinline__ void run_gemm(const uint4* __restrict__ wf, u32 sb,
                                         int lane, int r0, int cg, float acc[2][8][4])
{
    #pragma unroll
    for (int mt = 0; mt < 2; mt++)
        #pragma unroll
        for (int nt = 0; nt < 8; nt++)
            #pragma unroll
            for (int q = 0; q < 4; q++) acc[mt][nt][q] = 0.f;

    __syncthreads();                       // A writes (attn/epilogue) visible
    const int g = lane >> 3, r = lane & 7;
    const int arow = r0 + (g & 1)*8 + r;
    const int akb  = (g >> 1)*8;
    const int cg4  = cg * 4;

    uint4 b0h[4], b0l[4], b1h[4], b1l[4];
    u32 ah[2][4], al[2][4];
    LOADB(b0h, b0l, 0);
    #pragma unroll
    for (int c = 0; c < 16; c += 2) {
        LOADB(b1h, b1l, c + 1);
        lda(sb, arow, c*16 + akb, ah, al);
        mma_group(acc, ah, al, b0h, b0l);
        if (c + 2 < 16) LOADB(b0h, b0l, c + 2);
        lda(sb, arow, (c+1)*16 + akb, ah, al);
        mma_group(acc, ah, al, b1h, b1l);
    }
    __syncthreads();                       // all reads of A done before rewrite
}

// ---------------- fused kernel -----------------------------------------------
__global__ void __launch_bounds__(256, 1)
mma_fused(const float* __restrict__ fc1b, const float* __restrict__ fc2w,
          const float* __restrict__ fc2b, float* __restrict__ out)
{
    extern __shared__ char sm[];
    u32 sb = smem_u32(sm);
    const int tid = threadIdx.x, lane = tid & 31, w = tid >> 5;
    const int b = blockIdx.y, i0 = blockIdx.x * 64;
    const int r0 = (w & 1) * 32, cg = w >> 1, c0 = cg * 64;
    const int qr = lane >> 2, qc = (lane & 3) * 2;

    ((float*)(sm + S_F1B))[tid] = fc1b[tid];
    ((float*)(sm + S_F2W))[tid] = fc2w[tid];

    float acc[2][8][4];

    for (int br = 0; br < 2; br++) {
        const float* genc = br ? g_enc2 : g_enc1;
        const float* gaff = br ? g_affv : g_affa;
        const float* gX   = br ? g_Xv   : g_Xa;
        const uint4* wb   = g_wfrag + (size_t)(br * 3) * 16384;

        __syncthreads();
        ((float*)(sm + S_AFF))[tid] = gaff[b*256 + tid];
        __syncthreads();

        // ---- attn tile -> A hi/lo (rank-1 outer product) ----
        {
            int row = tid >> 2, cb = (tid & 3) * 64;
            float ev = genc[b*256 + i0 + row] * ATT_SCALE;
            const float* aff = (const float*)(sm + S_AFF);
            #pragma unroll 4
            for (int p = 0; p < 32; p++) {
                int col = cb + 2*p;
                float v0 = ftanh(ev * aff[col]), v1 = ftanh(ev * aff[col + 1]);
                u32 rh, rl; split2(v0, v1, rh, rl);
                u32 off = (u32)((row * A_STR + col) * 2);
                *(u32*)(sm + S_AHI + off) = rh;
                *(u32*)(sm + S_ALO + off) = rl;
            }
        }

        // ---- GEMM1: D = attn @ Wc^T ; A = relu(D + X) ----
        run_gemm(wb, sb, lane, r0, cg, acc);
        #pragma unroll
        for (int mt = 0; mt < 2; mt++)
            #pragma unroll
            for (int rs = 0; rs < 2; rs++) {
                int row = r0 + mt*16 + rs*8 + qr;
                #pragma unroll
                for (int nt = 0; nt < 8; nt++) {
                    int col = c0 + nt*8 + qc;
                    float2 xv = *(const float2*)(gX + (size_t)(i0 + row)*256 + col);
                    float v0 = fmaxf(acc[mt][nt][rs*2]   + xv.x, 0.f);
                    float v1 = fmaxf(acc[mt][nt][rs*2+1] + xv.y, 0.f);
                    u32 rh, rl; split2(v0, v1, rh, rl);
                    u32 off = (u32)((row * A_STR + col) * 2);
                    *(u32*)(sm + S_AHI + off) = rh;
                    *(u32*)(sm + S_ALO + off) = rl;
                }
            }

        // ---- GEMM2: D = H @ Wh^T ; A = D + enc ----
        run_gemm(wb + 16384, sb, lane, r0, cg, acc);
        #pragma unroll
        for (int mt = 0; mt < 2; mt++)
            #pragma unroll
            for (int rs = 0; rs < 2; rs++) {
                int row = r0 + mt*16 + rs*8 + qr;
                #pragma unroll
                for (int nt = 0; nt < 8; nt++) {
                    int col = c0 + nt*8 + qc;
                    float2 ev2 = *(const float2*)(genc + (size_t)(i0 + row)*256 + col);
                    float v0 = acc[mt][nt][rs*2]   + ev2.x;
                    float v1 = acc[mt][nt][rs*2+1] + ev2.y;
                    u32 rh, rl; split2(v0, v1, rh, rl);
                    u32 off = (u32)((row * A_STR + col) * 2);
                    *(u32*)(sm + S_AHI + off) = rh;
                    *(u32*)(sm + S_ALO + off) = rl;
                }
            }

        // ---- GEMM3: D = attn_enc @ fc1_half^T ----
        run_gemm(wb + 32768, sb, lane, r0, cg, acc);
        if (br == 0) {
            #pragma unroll
            for (int mt = 0; mt < 2; mt++)
                #pragma unroll
                for (int rs = 0; rs < 2; rs++) {
                    int row = r0 + mt*16 + rs*8 + qr;
                    #pragma unroll
                    for (int nt = 0; nt < 8; nt++) {
                        int col = c0 + nt*8 + qc;
                        *(float2*)(sm + S_PARK + (u32)((row*260 + col) * 4)) =
                            make_float2(acc[mt][nt][rs*2], acc[mt][nt][rs*2+1]);
                    }
                }
        } else {
            const float* f1bs = (const float*)(sm + S_F1B);
            const float* f2ws = (const float*)(sm + S_F2W);
            #pragma unroll
            for (int mt = 0; mt < 2; mt++)
                #pragma unroll
                for (int rs = 0; rs < 2; rs++) {
                    int row = r0 + mt*16 + rs*8 + qr;
                    float s = 0.f;
                    #pragma unroll
                    for (int nt = 0; nt < 8; nt++) {
                        int col = c0 + nt*8 + qc;
                        float2 pk = *(const float2*)(sm + S_PARK + (u32)((row*260 + col) * 4));
                        float h0 = fmaxf(acc[mt][nt][rs*2]   + pk.x + f1bs[col],     0.f);
                        float h1 = fmaxf(acc[mt][nt][rs*2+1] + pk.y + f1bs[col + 1], 0.f);
                        s = fmaf(h0, f2ws[col], s);
                        s = fmaf(h1, f2ws[col + 1], s);
                    }
                    s += __shfl_xor_sync(0xffffffffu, s, 1);
                    s += __shfl_xor_sync(0xffffffffu, s, 2);
                    if ((lane & 3) == 0)
                        ((float*)(sm + S_OSUM))[row*4 + cg] = s;
                }
            __syncthreads();
            if (tid < 64) {
                const float* os = (const float*)(sm + S_OSUM);
                out[b*256 + i0 + tid] =
                    os[tid*4] + os[tid*4+1] + os[tid*4+2] + os[tid*4+3] + fc2b[0];
            }
        }
        __syncthreads();
    }
}

// ---------------- launch -----------------------------------------------------
extern "C" void kernel_launch(void* const* d_in, const int* in_sizes, int n_in,
                              void* d_out, int out_size)
{
    (void)in_sizes; (void)n_in; (void)out_size;
    const float* f1     = (const float*)d_in[0];
    const float* f2     = (const float*)d_in[1];
    const float* enc1_w = (const float*)d_in[2];
    const float* enc1_b = (const float*)d_in[3];
    const float* enc2_w = (const float*)d_in[4];
    const float* enc2_b = (const float*)d_in[5];
    const float* affa_w = (const float*)d_in[6];
    const float* affv_w = (const float*)d_in[7];
    const float* wa_w   = (const float*)d_in[8];
    const float* wv_w   = (const float*)d_in[9];
    const float* wca_w  = (const float*)d_in[10];
    const float* wcv_w  = (const float*)d_in[11];
    const float* wha_w  = (const float*)d_in[12];
    const float* whv_w  = (const float*)d_in[13];
    const float* fc1_w  = (const float*)d_in[14];
    const float* fc1_b  = (const float*)d_in[15];
    const float* fc2_w  = (const float*)d_in[16];
    const float* fc2_b  = (const float*)d_in[17];
    float* out = (float*)d_out;

    cudaFuncSetAttribute(mma_fused, cudaFuncAttributeMaxDynamicSharedMemorySize, S_TOTAL);

    split_kernel<<<dim3(6, 16), 512>>>(wca_w, wcv_w, wha_w, whv_w, fc1_w);
    pre_enc_kernel<<<dim3(8, 4, 2), 256>>>(f1, f2, enc1_w, enc1_b, enc2_w, enc2_b);
    pre_aff_kernel<<<dim3(8, 4, 4), 256>>>(affa_w, affv_w, wa_w, wv_w);
    mma_fused<<<dim3(4, 256), 256, S_TOTAL>>>(fc1_b, fc2_w, fc2_b, out);
}

// round 11
// speedup vs baseline: 1.9391x; 1.0184x over previous
#include <cuda_runtime.h>
#include <cuda_bf16.h>
#include <cstdint>
#include <math.h>

#define ATT_SCALE 0.0625f
typedef uint32_t u32;

// ---------------- SMEM byte offsets ------------------------------------------
#define S_AHI   0                  // 64 x 264 bf16
#define S_ALO   33792
#define S_PARK  67584              // 64 x 260 fp32
#define S_AFF   134144             // 256 fp32
#define S_F1B   135168
#define S_F2W   136192
#define S_OSUM  137216             // 64 x 4 fp32
#define S_TOTAL 138240
#define A_STR   264                // bf16 per A row (pad: conflict-free ldmatrix)

// ---------------- device scratch ---------------------------------------------
__device__ float g_enc1[65536], g_enc2[65536];
__device__ float g_affa[65536], g_affv[65536];
__device__ float g_Xa[65536],   g_Xv[65536];
// 6 weights x 16 chunks x 16 colgroups x (hi 32 + lo 32) uint4, fragment order
__device__ uint4 g_wfrag[6 * 16384];

// ---------------- small helpers ----------------------------------------------
__device__ __forceinline__ u32 smem_u32(const void* p) {
    u32 a;
    asm("{ .reg .u64 t; cvta.to.shared.u64 t, %1; cvt.u32.u64 %0, t; }" : "=r"(a) : "l"(p));
    return a;
}
__device__ __forceinline__ void ldsm4(u32 addr, u32* d) {
    asm volatile("ldmatrix.sync.aligned.m8n8.x4.shared.b16 {%0,%1,%2,%3}, [%4];"
        : "=r"(d[0]), "=r"(d[1]), "=r"(d[2]), "=r"(d[3]) : "r"(addr));
}
__device__ __forceinline__ void mma_bf16(float* c, const u32* a, const u32* b) {
    asm volatile("mma.sync.aligned.m16n8k16.row.col.f32.bf16.bf16.f32 "
        "{%0,%1,%2,%3}, {%4,%5,%6,%7}, {%8,%9}, {%0,%1,%2,%3};"
        : "+f"(c[0]), "+f"(c[1]), "+f"(c[2]), "+f"(c[3])
        : "r"(a[0]), "r"(a[1]), "r"(a[2]), "r"(a[3]), "r"(b[0]), "r"(b[1]));
}
__device__ __forceinline__ void split2(float v0, float v1, u32& rh, u32& rl) {
    __nv_bfloat16 h0 = __float2bfloat16(v0), h1 = __float2bfloat16(v1);
    __nv_bfloat16 l0 = __float2bfloat16(v0 - __bfloat162float(h0));
    __nv_bfloat16 l1 = __float2bfloat16(v1 - __bfloat162float(h1));
    rh = (u32)__bfloat16_as_ushort(h0) | ((u32)__bfloat16_as_ushort(h1) << 16);
    rl = (u32)__bfloat16_as_ushort(l0) | ((u32)__bfloat16_as_ushort(l1) << 16);
}
__device__ __forceinline__ float ftanh(float x) {
    float t = __expf(fminf(2.0f * x, 80.0f));
    return __fdividef(t - 1.0f, t + 1.0f);
}

// ---------------- prep GEMMs (SIMT fp32, known-correct) -----------------------
__device__ __forceinline__ void small_gemm(const float* __restrict__ A,
                                           const float* __restrict__ W,
                                           const float* __restrict__ bias,
                                           float* __restrict__ C, int K)
{
    __shared__ float As[32][17];
    __shared__ float Ws[64][17];
    const int i0 = blockIdx.x * 32, j0 = blockIdx.y * 64;
    const int tid = threadIdx.x;
    const int tx = tid & 15, ty = tid >> 4;
    const int ar = tid >> 2, ak = (tid & 3) * 4;
    float acc[2][4] = {};
    for (int k0 = 0; k0 < K; k0 += 16) {
        float4 av = make_float4(0.f, 0.f, 0.f, 0.f);
        if (tid < 128) av = *(const float4*)(A + (size_t)(i0 + ar) * K + k0 + ak);
        float4 wv = *(const float4*)(W + (size_t)(j0 + ar) * K + k0 + ak);
        __syncthreads();
        if (tid < 128) {
            As[ar][ak] = av.x; As[ar][ak+1] = av.y; As[ar][ak+2] = av.z; As[ar][ak+3] = av.w;
        }
        Ws[ar][ak] = wv.x; Ws[ar][ak+1] = wv.y; Ws[ar][ak+2] = wv.z; Ws[ar][ak+3] = wv.w;
        __syncthreads();
        #pragma unroll
        for (int kk = 0; kk < 16; kk++) {
            float a0 = As[ty*2][kk], a1 = As[ty*2+1][kk];
            float b0 = Ws[tx*4][kk], b1 = Ws[tx*4+1][kk];
            float b2 = Ws[tx*4+2][kk], b3 = Ws[tx*4+3][kk];
            acc[0][0] = fmaf(a0,b0,acc[0][0]); acc[0][1] = fmaf(a0,b1,acc[0][1]);
            acc[0][2] = fmaf(a0,b2,acc[0][2]); acc[0][3] = fmaf(a0,b3,acc[0][3]);
            acc[1][0] = fmaf(a1,b0,acc[1][0]); acc[1][1] = fmaf(a1,b1,acc[1][1]);
            acc[1][2] = fmaf(a1,b2,acc[1][2]); acc[1][3] = fmaf(a1,b3,acc[1][3]);
        }
    }
    #pragma unroll
    for (int u = 0; u < 2; u++)
        #pragma unroll
        for (int v = 0; v < 4; v++) {
            int j = j0 + tx*4 + v;
            float x = acc[u][v];
            if (bias) x += bias[j];
            C[(size_t)(i0 + ty*2 + u) * 256 + j] = x;
        }
}

__global__ void pre_enc_kernel(const float* __restrict__ f1, const float* __restrict__ f2,
                               const float* __restrict__ w1, const float* __restrict__ b1,
                               const float* __restrict__ w2, const float* __restrict__ b2)
{
    if (blockIdx.z == 0) small_gemm(f1, w1, b1, g_enc1, 768);
    else                 small_gemm(f2, w2, b2, g_enc2, 768);
}

__global__ void pre_aff_kernel(const float* __restrict__ affa, const float* __restrict__ affv,
                               const float* __restrict__ wa,   const float* __restrict__ wv)
{
    int z = blockIdx.z;
    const float* A = (z == 0 || z == 2) ? g_enc1 : g_enc2;
    const float* W = (z == 0) ? affa : (z == 1) ? affv : (z == 2) ? wa : wv;
    float*       C = (z == 0) ? g_affa : (z == 1) ? g_affv : (z == 2) ? g_Xa : g_Xv;
    small_gemm(A, W, nullptr, C, 256);
}

// ---------------- weight split: fp32 -> bf16 hi/lo FRAGMENT layout ------------
// For (w, chunk c, colgroup jc): 512B hi block + 512B lo block. Lane l's uint4 =
// mma B frag th[0..3]: {n=jc*16+l/4, k=c*16+(l%4)*2}, {n, k+8}, {n+8, k}, {n+8, k+8}.
__global__ void split_kernel(const float* __restrict__ wca, const float* __restrict__ wcv,
                             const float* __restrict__ wha, const float* __restrict__ whv,
                             const float* __restrict__ fc1w)
{
    int w = blockIdx.x, c = blockIdx.y;
    int jc = threadIdx.x >> 5, lane = threadIdx.x & 31;
    const float* src; int stride = 256, co = 0;
    switch (w) {
        case 0: src = wca; break;
        case 1: src = wha; break;
        case 2: src = fc1w; stride = 512; break;
        case 3: src = wcv; break;
        case 4: src = whv; break;
        default: src = fc1w; stride = 512; co = 256; break;
    }
    int n0 = jc * 16 + (lane >> 2);
    int k0 = c * 16 + (lane & 3) * 2;
    const float* r0 = src + (size_t)n0 * stride + co;
    const float* r1 = src + (size_t)(n0 + 8) * stride + co;
    uint4 hv, lv;
    split2(r0[k0],     r0[k0 + 1], hv.x, lv.x);
    split2(r0[k0 + 8], r0[k0 + 9], hv.y, lv.y);
    split2(r1[k0],     r1[k0 + 1], hv.z, lv.z);
    split2(r1[k0 + 8], r1[k0 + 9], hv.w, lv.w);
    uint4* dst = g_wfrag + ((size_t)(w * 16 + c) * 16 + jc) * 64 + lane;
    dst[0]  = hv;
    dst[32] = lv;
}

// ---------------- tensor-core mainloop ---------------------------------------
__device__ __forceinline__ void lda(u32 sb, int arow, int akof, u32 ah[2][4], u32 al[2][4]) {
    #pragma unroll
    for (int mt = 0; mt < 2; mt++) {
        u32 ao = sb + S_AHI + (u32)(((arow + mt*16) * A_STR + akof) * 2);
        ldsm4(ao, ah[mt]);
        ldsm4(ao + (S_ALO - S_AHI), al[mt]);
    }
}
// Pass-outermost ordering: each acc quad is revisited only after 16 independent
// HMMAs, so the tensor pipe never stalls on accumulator RAW latency.
__device__ __forceinline__ void mma_group(float acc[2][8][4], u32 ah[2][4], u32 al[2][4],
                                          uint4 bh[4], uint4 bl[4]) {
    #pragma unroll
    for (int np = 0; np < 4; np++) {
        const u32* th = (const u32*)&bh[np];
        #pragma unroll
        for (int mt = 0; mt < 2; mt++) {
            mma_bf16(acc[mt][np*2],   ah[mt], th);
            mma_bf16(acc[mt][np*2+1], ah[mt], th + 2);
        }
    }
    #pragma unroll
    for (int np = 0; np < 4; np++) {
        const u32* th = (const u32*)&bh[np];
        #pragma unroll
        for (int mt = 0; mt < 2; mt++) {
            mma_bf16(acc[mt][np*2],   al[mt], th);
            mma_bf16(acc[mt][np*2+1], al[mt], th + 2);
        }
    }
    #pragma unroll
    for (int np = 0; np < 4; np++) {
        const u32* tl = (const u32*)&bl[np];
        #pragma unroll
        for (int mt = 0; mt < 2; mt++) {
            mma_bf16(acc[mt][np*2],   ah[mt], tl);
            mma_bf16(acc[mt][np*2+1], ah[mt], tl + 2);
        }
    }
}
#define LOADB(bh, bl, cc) do { \
    _Pragma("unroll") \
    for (int np = 0; np < 4; np++) { \
        const uint4* p = wf + ((size_t)(cc) * 16 + cg4 + np) * 64 + lane; \
        bh[np] = __ldg(p); bl[np] = __ldg(p + 32); \
    } \
} while (0)

// C tile: rows [r0,+32) of the CTA's 64, cols [cg*64,+64). No barriers inside
// the k-loop — B comes straight from GMEM, A is read-only SMEM.
__device__ __forceinline__ void run_gemm(const uint4* __restrict__ wf, u32 sb,
                                         int lane, int r0, int cg, float acc[2][8][4])
{
    #pragma unroll
    for (int mt = 0; mt < 2; mt++)
        #pragma unroll
        for (int nt = 0; nt < 8; nt++)
            #pragma unroll
            for (int q = 0; q < 4; q++) acc[mt][nt][q] = 0.f;

    __syncthreads();                       // A writes (attn/epilogue) visible
    const int g = lane >> 3, r = lane & 7;
    const int arow = r0 + (g & 1)*8 + r;
    const int akb  = (g >> 1)*8;
    const int cg4  = cg * 4;

    uint4 b0h[4], b0l[4], b1h[4], b1l[4];
    u32 ah[2][4], al[2][4];
    LOADB(b0h, b0l, 0);
    #pragma unroll
    for (int c = 0; c < 16; c += 2) {
        LOADB(b1h, b1l, c + 1);
        lda(sb, arow, c*16 + akb, ah, al);
        mma_group(acc, ah, al, b0h, b0l);
        if (c + 2 < 16) LOADB(b0h, b0l, c + 2);
        lda(sb, arow, (c+1)*16 + akb, ah, al);
        mma_group(acc, ah, al, b1h, b1l);
    }
    __syncthreads();                       // all reads of A done before rewrite
}

// ---------------- fused kernel -----------------------------------------------
__global__ void __launch_bounds__(256, 1)
mma_fused(const float* __restrict__ fc1b, const float* __restrict__ fc2w,
          const float* __restrict__ fc2b, float* __restrict__ out)
{
    extern __shared__ char sm[];
    u32 sb = smem_u32(sm);
    const int tid = threadIdx.x, lane = tid & 31, w = tid >> 5;
    const int b = blockIdx.y, i0 = blockIdx.x * 64;
    const int r0 = (w & 1) * 32, cg = w >> 1, c0 = cg * 64;
    const int qr = lane >> 2, qc = (lane & 3) * 2;

    ((float*)(sm + S_F1B))[tid] = fc1b[tid];
    ((float*)(sm + S_F2W))[tid] = fc2w[tid];

    float acc[2][8][4];

    for (int br = 0; br < 2; br++) {
        const float* genc = br ? g_enc2 : g_enc1;
        const float* gaff = br ? g_affv : g_affa;
        const float* gX   = br ? g_Xv   : g_Xa;
        const uint4* wb   = g_wfrag + (size_t)(br * 3) * 16384;

        __syncthreads();
        ((float*)(sm + S_AFF))[tid] = gaff[b*256 + tid];
        __syncthreads();

        // ---- attn tile -> A hi/lo (rank-1 outer product) ----
        {
            int row = tid >> 2, cb = (tid & 3) * 64;
            float ev = genc[b*256 + i0 + row] * ATT_SCALE;
            const float* aff = (const float*)(sm + S_AFF);
            #pragma unroll 4
            for (int p = 0; p < 32; p++) {
                int col = cb + 2*p;
                float v0 = ftanh(ev * aff[col]), v1 = ftanh(ev * aff[col + 1]);
                u32 rh, rl; split2(v0, v1, rh, rl);
                u32 off = (u32)((row * A_STR + col) * 2);
                *(u32*)(sm + S_AHI + off) = rh;
                *(u32*)(sm + S_ALO + off) = rl;
            }
        }

        // ---- GEMM1: D = attn @ Wc^T ; A = relu(D + X) ----
        run_gemm(wb, sb, lane, r0, cg, acc);
        #pragma unroll
        for (int mt = 0; mt < 2; mt++)
            #pragma unroll
            for (int rs = 0; rs < 2; rs++) {
                int row = r0 + mt*16 + rs*8 + qr;
                #pragma unroll
                for (int nt = 0; nt < 8; nt++) {
                    int col = c0 + nt*8 + qc;
                    float2 xv = *(const float2*)(gX + (size_t)(i0 + row)*256 + col);
                    float v0 = fmaxf(acc[mt][nt][rs*2]   + xv.x, 0.f);
                    float v1 = fmaxf(acc[mt][nt][rs*2+1] + xv.y, 0.f);
                    u32 rh, rl; split2(v0, v1, rh, rl);
                    u32 off = (u32)((row * A_STR + col) * 2);
                    *(u32*)(sm + S_AHI + off) = rh;
                    *(u32*)(sm + S_ALO + off) = rl;
                }
            }

        // ---- GEMM2: D = H @ Wh^T ; A = D + enc ----
        run_gemm(wb + 16384, sb, lane, r0, cg, acc);
        #pragma unroll
        for (int mt = 0; mt < 2; mt++)
            #pragma unroll
            for (int rs = 0; rs < 2; rs++) {
                int row = r0 + mt*16 + rs*8 + qr;
                #pragma unroll
                for (int nt = 0; nt < 8; nt++) {
                    int col = c0 + nt*8 + qc;
                    float2 ev2 = *(const float2*)(genc + (size_t)(i0 + row)*256 + col);
                    float v0 = acc[mt][nt][rs*2]   + ev2.x;
                    float v1 = acc[mt][nt][rs*2+1] + ev2.y;
                    u32 rh, rl; split2(v0, v1, rh, rl);
                    u32 off = (u32)((row * A_STR + col) * 2);
                    *(u32*)(sm + S_AHI + off) = rh;
                    *(u32*)(sm + S_ALO + off) = rl;
                }
            }

        // ---- GEMM3: D = attn_enc @ fc1_half^T ----
        run_gemm(wb + 32768, sb, lane, r0, cg, acc);
        if (br == 0) {
            #pragma unroll
            for (int mt = 0; mt < 2; mt++)
                #pragma unroll
                for (int rs = 0; rs < 2; rs++) {
                    int row = r0 + mt*16 + rs*8 + qr;
                    #pragma unroll
                    for (int nt = 0; nt < 8; nt++) {
                        int col = c0 + nt*8 + qc;
                        *(float2*)(sm + S_PARK + (u32)((row*260 + col) * 4)) =
                            make_float2(acc[mt][nt][rs*2], acc[mt][nt][rs*2+1]);
                    }
                }
        } else {
            const float* f1bs = (const float*)(sm + S_F1B);
            const float* f2ws = (const float*)(sm + S_F2W);
            #pragma unroll
            for (int mt = 0; mt < 2; mt++)
                #pragma unroll
                for (int rs = 0; rs < 2; rs++) {
                    int row = r0 + mt*16 + rs*8 + qr;
                    float s = 0.f;
                    #pragma unroll
                    for (int nt = 0; nt < 8; nt++) {
                        int col = c0 + nt*8 + qc;
                        float2 pk = *(const float2*)(sm + S_PARK + (u32)((row*260 + col) * 4));
                        float h0 = fmaxf(acc[mt][nt][rs*2]   + pk.x + f1bs[col],     0.f);
                        float h1 = fmaxf(acc[mt][nt][rs*2+1] + pk.y + f1bs[col + 1], 0.f);
                        s = fmaf(h0, f2ws[col], s);
                        s = fmaf(h1, f2ws[col + 1], s);
                    }
                    s += __shfl_xor_sync(0xffffffffu, s, 1);
                    s += __shfl_xor_sync(0xffffffffu, s, 2);
                    if ((lane & 3) == 0)
                        ((float*)(sm + S_OSUM))[row*4 + cg] = s;
                }
            __syncthreads();
            if (tid < 64) {
                const float* os = (const float*)(sm + S_OSUM);
                out[b*256 + i0 + tid] =
                    os[tid*4] + os[tid*4+1] + os[tid*4+2] + os[tid*4+3] + fc2b[0];
            }
        }
        __syncthreads();
    }
}

// ---------------- launch -----------------------------------------------------
extern "C" void kernel_launch(void* const* d_in, const int* in_sizes, int n_in,
                              void* d_out, int out_size)
{
    (void)in_sizes; (void)n_in; (void)out_size;
    const float* f1     = (const float*)d_in[0];
    const float* f2     = (const float*)d_in[1];
    const float* enc1_w = (const float*)d_in[2];
    const float* enc1_b = (const float*)d_in[3];
    const float* enc2_w = (const float*)d_in[4];
    const float* enc2_b = (const float*)d_in[5];
    const float* affa_w = (const float*)d_in[6];
    const float* affv_w = (const float*)d_in[7];
    const float* wa_w   = (const float*)d_in[8];
    const float* wv_w   = (const float*)d_in[9];
    const float* wca_w  = (const float*)d_in[10];
    const float* wcv_w  = (const float*)d_in[11];
    const float* wha_w  = (const float*)d_in[12];
    const float* whv_w  = (const float*)d_in[13];
    const float* fc1_w  = (const float*)d_in[14];
    const float* fc1_b  = (const float*)d_in[15];
    const float* fc2_w  = (const float*)d_in[16];
    const float* fc2_b  = (const float*)d_in[17];
    float* out = (float*)d_out;

    cudaFuncSetAttribute(mma_fused, cudaFuncAttributeMaxDynamicSharedMemorySize, S_TOTAL);

    split_kernel<<<dim3(6, 16), 512>>>(wca_w, wcv_w, wha_w, whv_w, fc1_w);
    pre_enc_kernel<<<dim3(8, 4, 2), 256>>>(f1, f2, enc1_w, enc1_b, enc2_w, enc2_b);
    pre_aff_kernel<<<dim3(8, 4, 4), 256>>>(affa_w, affv_w, wa_w, wv_w);
    mma_fused<<<dim3(4, 256), 256, S_TOTAL>>>(fc1_b, fc2_w, fc2_b, out);
}

// round 12
// speedup vs baseline: 2.4165x; 1.2462x over previous
#include <cuda_runtime.h>
#include <cuda_fp16.h>
#include <cstdint>
#include <math.h>

#define ATT_SCALE 0.0625f
typedef uint32_t u32;

// ---------------- SMEM byte offsets ------------------------------------------
#define S_AHI   0                  // 64 x 264 fp16
#define S_ALO   33792
#define S_PARK  67584              // 64 x 260 fp32
#define S_AFF   134144             // 256 fp32
#define S_F1B   135168
#define S_F2W   136192
#define S_OSUM  137216             // 64 x 4 fp32
#define S_TOTAL 138240
#define A_STR   264                // fp16 per A row (pad: conflict-free ldmatrix)

// ---------------- device scratch ---------------------------------------------
__device__ float g_enc1[65536], g_enc2[65536];
__device__ float g_affa[65536], g_affv[65536];
__device__ float g_Xa[65536],   g_Xv[65536];
// 6 weights x 16 chunks x 16 colgroups x 32 uint4 (fp16, fragment order)
__device__ uint4 g_wfrag[6 * 8192];

// ---------------- small helpers ----------------------------------------------
__device__ __forceinline__ u32 smem_u32(const void* p) {
    u32 a;
    asm("{ .reg .u64 t; cvta.to.shared.u64 t, %1; cvt.u32.u64 %0, t; }" : "=r"(a) : "l"(p));
    return a;
}
__device__ __forceinline__ void ldsm4(u32 addr, u32* d) {
    asm volatile("ldmatrix.sync.aligned.m8n8.x4.shared.b16 {%0,%1,%2,%3}, [%4];"
        : "=r"(d[0]), "=r"(d[1]), "=r"(d[2]), "=r"(d[3]) : "r"(addr));
}
__device__ __forceinline__ void mma_f16(float* c, const u32* a, const u32* b) {
    asm volatile("mma.sync.aligned.m16n8k16.row.col.f32.f16.f16.f32 "
        "{%0,%1,%2,%3}, {%4,%5,%6,%7}, {%8,%9}, {%0,%1,%2,%3};"
        : "+f"(c[0]), "+f"(c[1]), "+f"(c[2]), "+f"(c[3])
        : "r"(a[0]), "r"(a[1]), "r"(a[2]), "r"(a[3]), "r"(b[0]), "r"(b[1]));
}
// fp16 hi/lo split of a float pair
__device__ __forceinline__ void split2(float v0, float v1, u32& rh, u32& rl) {
    __half h0 = __float2half(v0), h1 = __float2half(v1);
    __half l0 = __float2half(v0 - __half2float(h0));
    __half l1 = __float2half(v1 - __half2float(h1));
    rh = (u32)__half_as_ushort(h0) | ((u32)__half_as_ushort(h1) << 16);
    rl = (u32)__half_as_ushort(l0) | ((u32)__half_as_ushort(l1) << 16);
}
// fp16 round (hi only) of a float pair
__device__ __forceinline__ u32 pack2(float v0, float v1) {
    __half h0 = __float2half(v0), h1 = __float2half(v1);
    return (u32)__half_as_ushort(h0) | ((u32)__half_as_ushort(h1) << 16);
}
__device__ __forceinline__ float ftanh(float x) {
    float t = __expf(fminf(2.0f * x, 80.0f));
    return __fdividef(t - 1.0f, t + 1.0f);
}

// ---------------- prep GEMMs (SIMT fp32, known-correct) -----------------------
__device__ __forceinline__ void small_gemm(const float* __restrict__ A,
                                           const float* __restrict__ W,
                                           const float* __restrict__ bias,
                                           float* __restrict__ C, int K)
{
    __shared__ float As[32][17];
    __shared__ float Ws[64][17];
    const int i0 = blockIdx.x * 32, j0 = blockIdx.y * 64;
    const int tid = threadIdx.x;
    const int tx = tid & 15, ty = tid >> 4;
    const int ar = tid >> 2, ak = (tid & 3) * 4;
    float acc[2][4] = {};
    for (int k0 = 0; k0 < K; k0 += 16) {
        float4 av = make_float4(0.f, 0.f, 0.f, 0.f);
        if (tid < 128) av = *(const float4*)(A + (size_t)(i0 + ar) * K + k0 + ak);
        float4 wv = *(const float4*)(W + (size_t)(j0 + ar) * K + k0 + ak);
        __syncthreads();
        if (tid < 128) {
            As[ar][ak] = av.x; As[ar][ak+1] = av.y; As[ar][ak+2] = av.z; As[ar][ak+3] = av.w;
        }
        Ws[ar][ak] = wv.x; Ws[ar][ak+1] = wv.y; Ws[ar][ak+2] = wv.z; Ws[ar][ak+3] = wv.w;
        __syncthreads();
        #pragma unroll
        for (int kk = 0; kk < 16; kk++) {
            float a0 = As[ty*2][kk], a1 = As[ty*2+1][kk];
            float b0 = Ws[tx*4][kk], b1 = Ws[tx*4+1][kk];
            float b2 = Ws[tx*4+2][kk], b3 = Ws[tx*4+3][kk];
            acc[0][0] = fmaf(a0,b0,acc[0][0]); acc[0][1] = fmaf(a0,b1,acc[0][1]);
            acc[0][2] = fmaf(a0,b2,acc[0][2]); acc[0][3] = fmaf(a0,b3,acc[0][3]);
            acc[1][0] = fmaf(a1,b0,acc[1][0]); acc[1][1] = fmaf(a1,b1,acc[1][1]);
            acc[1][2] = fmaf(a1,b2,acc[1][2]); acc[1][3] = fmaf(a1,b3,acc[1][3]);
        }
    }
    #pragma unroll
    for (int u = 0; u < 2; u++)
        #pragma unroll
        for (int v = 0; v < 4; v++) {
            int j = j0 + tx*4 + v;
            float x = acc[u][v];
            if (bias) x += bias[j];
            C[(size_t)(i0 + ty*2 + u) * 256 + j] = x;
        }
}

__global__ void pre_enc_kernel(const float* __restrict__ f1, const float* __restrict__ f2,
                               const float* __restrict__ w1, const float* __restrict__ b1,
                               const float* __restrict__ w2, const float* __restrict__ b2)
{
    if (blockIdx.z == 0) small_gemm(f1, w1, b1, g_enc1, 768);
    else                 small_gemm(f2, w2, b2, g_enc2, 768);
}

__global__ void pre_aff_kernel(const float* __restrict__ affa, const float* __restrict__ affv,
                               const float* __restrict__ wa,   const float* __restrict__ wv)
{
    int z = blockIdx.z;
    const float* A = (z == 0 || z == 2) ? g_enc1 : g_enc2;
    const float* W = (z == 0) ? affa : (z == 1) ? affv : (z == 2) ? wa : wv;
    float*       C = (z == 0) ? g_affa : (z == 1) ? g_affv : (z == 2) ? g_Xa : g_Xv;
    small_gemm(A, W, nullptr, C, 256);
}

// ---------------- weight split: fp32 -> fp16 FRAGMENT layout ------------------
// For (w, chunk c, colgroup jc): 512B block. Lane l's uint4 = mma B frag
// th[0..3]: {n=jc*16+l/4, k=c*16+(l%4)*2}, {n, k+8}, {n+8, k}, {n+8, k+8}.
__global__ void split_kernel(const float* __restrict__ wca, const float* __restrict__ wcv,
                             const float* __restrict__ wha, const float* __restrict__ whv,
                             const float* __restrict__ fc1w)
{
    int w = blockIdx.x, c = blockIdx.y;
    int jc = threadIdx.x >> 5, lane = threadIdx.x & 31;
    const float* src; int stride = 256, co = 0;
    switch (w) {
        case 0: src = wca; break;
        case 1: src = wha; break;
        case 2: src = fc1w; stride = 512; break;
        case 3: src = wcv; break;
        case 4: src = whv; break;
        default: src = fc1w; stride = 512; co = 256; break;
    }
    int n0 = jc * 16 + (lane >> 2);
    int k0 = c * 16 + (lane & 3) * 2;
    const float* r0 = src + (size_t)n0 * stride + co;
    const float* r1 = src + (size_t)(n0 + 8) * stride + co;
    uint4 hv;
    hv.x = pack2(r0[k0],     r0[k0 + 1]);
    hv.y = pack2(r0[k0 + 8], r0[k0 + 9]);
    hv.z = pack2(r1[k0],     r1[k0 + 1]);
    hv.w = pack2(r1[k0 + 8], r1[k0 + 9]);
    g_wfrag[((size_t)(w * 16 + c) * 16 + jc) * 32 + lane] = hv;
}

// ---------------- tensor-core mainloop ---------------------------------------
__device__ __forceinline__ void lda(u32 sb, int arow, int akof, u32 ah[2][4], u32 al[2][4]) {
    #pragma unroll
    for (int mt = 0; mt < 2; mt++) {
        u32 ao = sb + S_AHI + (u32)(((arow + mt*16) * A_STR + akof) * 2);
        ldsm4(ao, ah[mt]);
        ldsm4(ao + (S_ALO - S_AHI), al[mt]);
    }
}
// 2-pass fp16: D = Ahi*B + Alo*B. Pass-outermost: 16 independent HMMAs between
// revisits of any accumulator quad.
__device__ __forceinline__ void mma_group(float acc[2][8][4], u32 ah[2][4], u32 al[2][4],
                                          uint4 bh[4]) {
    #pragma unroll
    for (int np = 0; np < 4; np++) {
        const u32* th = (const u32*)&bh[np];
        #pragma unroll
        for (int mt = 0; mt < 2; mt++) {
            mma_f16(acc[mt][np*2],   ah[mt], th);
            mma_f16(acc[mt][np*2+1], ah[mt], th + 2);
        }
    }
    #pragma unroll
    for (int np = 0; np < 4; np++) {
        const u32* th = (const u32*)&bh[np];
        #pragma unroll
        for (int mt = 0; mt < 2; mt++) {
            mma_f16(acc[mt][np*2],   al[mt], th);
            mma_f16(acc[mt][np*2+1], al[mt], th + 2);
        }
    }
}
#define LOADB(bh, cc) do { \
    _Pragma("unroll") \
    for (int np = 0; np < 4; np++) { \
        bh[np] = __ldg(wf + ((size_t)(cc) * 16 + cg4 + np) * 32 + lane); \
    } \
} while (0)

// C tile: rows [r0,+32) of the CTA's 64, cols [cg*64,+64). No barriers inside
// the k-loop — B comes straight from GMEM, A is read-only SMEM.
__device__ __forceinline__ void run_gemm(const uint4* __restrict__ wf, u32 sb,
                                         int lane, int r0, int cg, float acc[2][8][4])
{
    #pragma unroll
    for (int mt = 0; mt < 2; mt++)
        #pragma unroll
        for (int nt = 0; nt < 8; nt++)
            #pragma unroll
            for (int q = 0; q < 4; q++) acc[mt][nt][q] = 0.f;

    __syncthreads();                       // A writes (attn/epilogue) visible
    const int g = lane >> 3, r = lane & 7;
    const int arow = r0 + (g & 1)*8 + r;
    const int akb  = (g >> 1)*8;
    const int cg4  = cg * 4;

    uint4 b0h[4], b1h[4];
    u32 ah[2][4], al[2][4];
    LOADB(b0h, 0);
    #pragma unroll
    for (int c = 0; c < 16; c += 2) {
        LOADB(b1h, c + 1);
        lda(sb, arow, c*16 + akb, ah, al);
        mma_group(acc, ah, al, b0h);
        if (c + 2 < 16) LOADB(b0h, c + 2);
        lda(sb, arow, (c+1)*16 + akb, ah, al);
        mma_group(acc, ah, al, b1h);
    }
    __syncthreads();                       // all reads of A done before rewrite
}

// ---------------- fused kernel -----------------------------------------------
__global__ void __launch_bounds__(256, 1)
mma_fused(const float* __restrict__ fc1b, const float* __restrict__ fc2w,
          const float* __restrict__ fc2b, float* __restrict__ out)
{
    extern __shared__ char sm[];
    u32 sb = smem_u32(sm);
    const int tid = threadIdx.x, lane = tid & 31, w = tid >> 5;
    const int b = blockIdx.y, i0 = blockIdx.x * 64;
    const int r0 = (w & 1) * 32, cg = w >> 1, c0 = cg * 64;
    const int qr = lane >> 2, qc = (lane & 3) * 2;

    ((float*)(sm + S_F1B))[tid] = fc1b[tid];
    ((float*)(sm + S_F2W))[tid] = fc2w[tid];

    float acc[2][8][4];

    for (int br = 0; br < 2; br++) {
        const float* genc = br ? g_enc2 : g_enc1;
        const float* gaff = br ? g_affv : g_affa;
        const float* gX   = br ? g_Xv   : g_Xa;
        const uint4* wb   = g_wfrag + (size_t)(br * 3) * 8192;

        __syncthreads();
        ((float*)(sm + S_AFF))[tid] = gaff[b*256 + tid];
        __syncthreads();

        // ---- attn tile -> A hi/lo (rank-1 outer product) ----
        {
            int row = tid >> 2, cb = (tid & 3) * 64;
            float ev = genc[b*256 + i0 + row] * ATT_SCALE;
            const float* aff = (const float*)(sm + S_AFF);
            #pragma unroll 4
            for (int p = 0; p < 32; p++) {
                int col = cb + 2*p;
                float v0 = ftanh(ev * aff[col]), v1 = ftanh(ev * aff[col + 1]);
                u32 rh, rl; split2(v0, v1, rh, rl);
                u32 off = (u32)((row * A_STR + col) * 2);
                *(u32*)(sm + S_AHI + off) = rh;
                *(u32*)(sm + S_ALO + off) = rl;
            }
        }

        // ---- GEMM1: D = attn @ Wc^T ; A = relu(D + X) ----
        run_gemm(wb, sb, lane, r0, cg, acc);
        #pragma unroll
        for (int mt = 0; mt < 2; mt++)
            #pragma unroll
            for (int rs = 0; rs < 2; rs++) {
                int row = r0 + mt*16 + rs*8 + qr;
                #pragma unroll
                for (int nt = 0; nt < 8; nt++) {
                    int col = c0 + nt*8 + qc;
                    float2 xv = *(const float2*)(gX + (size_t)(i0 + row)*256 + col);
                    float v0 = fmaxf(acc[mt][nt][rs*2]   + xv.x, 0.f);
                    float v1 = fmaxf(acc[mt][nt][rs*2+1] + xv.y, 0.f);
                    u32 rh, rl; split2(v0, v1, rh, rl);
                    u32 off = (u32)((row * A_STR + col) * 2);
                    *(u32*)(sm + S_AHI + off) = rh;
                    *(u32*)(sm + S_ALO + off) = rl;
                }
            }

        // ---- GEMM2: D = H @ Wh^T ; A = D + enc ----
        run_gemm(wb + 8192, sb, lane, r0, cg, acc);
        #pragma unroll
        for (int mt = 0; mt < 2; mt++)
            #pragma unroll
            for (int rs = 0; rs < 2; rs++) {
                int row = r0 + mt*16 + rs*8 + qr;
                #pragma unroll
                for (int nt = 0; nt < 8; nt++) {
                    int col = c0 + nt*8 + qc;
                    float2 ev2 = *(const float2*)(genc + (size_t)(i0 + row)*256 + col);
                    float v0 = acc[mt][nt][rs*2]   + ev2.x;
                    float v1 = acc[mt][nt][rs*2+1] + ev2.y;
                    u32 rh, rl; split2(v0, v1, rh, rl);
                    u32 off = (u32)((row * A_STR + col) * 2);
                    *(u32*)(sm + S_AHI + off) = rh;
                    *(u32*)(sm + S_ALO + off) = rl;
                }
            }

        // ---- GEMM3: D = attn_enc @ fc1_half^T ----
        run_gemm(wb + 16384, sb, lane, r0, cg, acc);
        if (br == 0) {
            #pragma unroll
            for (int mt = 0; mt < 2; mt++)
                #pragma unroll
                for (int rs = 0; rs < 2; rs++) {
                    int row = r0 + mt*16 + rs*8 + qr;
                    #pragma unroll
                    for (int nt = 0; nt < 8; nt++) {
                        int col = c0 + nt*8 + qc;
                        *(float2*)(sm + S_PARK + (u32)((row*260 + col) * 4)) =
                            make_float2(acc[mt][nt][rs*2], acc[mt][nt][rs*2+1]);
                    }
                }
        } else {
            const float* f1bs = (const float*)(sm + S_F1B);
            const float* f2ws = (const float*)(sm + S_F2W);
            #pragma unroll
            for (int mt = 0; mt < 2; mt++)
                #pragma unroll
                for (int rs = 0; rs < 2; rs++) {
                    int row = r0 + mt*16 + rs*8 + qr;
                    float s = 0.f;
                    #pragma unroll
                    for (int nt = 0; nt < 8; nt++) {
                        int col = c0 + nt*8 + qc;
                        float2 pk = *(const float2*)(sm + S_PARK + (u32)((row*260 + col) * 4));
                        float h0 = fmaxf(acc[mt][nt][rs*2]   + pk.x + f1bs[col],     0.f);
                        float h1 = fmaxf(acc[mt][nt][rs*2+1] + pk.y + f1bs[col + 1], 0.f);
                        s = fmaf(h0, f2ws[col], s);
                        s = fmaf(h1, f2ws[col + 1], s);
                    }
                    s += __shfl_xor_sync(0xffffffffu, s, 1);
                    s += __shfl_xor_sync(0xffffffffu, s, 2);
                    if ((lane & 3) == 0)
                        ((float*)(sm + S_OSUM))[row*4 + cg] = s;
                }
            __syncthreads();
            if (tid < 64) {
                const float* os = (const float*)(sm + S_OSUM);
                out[b*256 + i0 + tid] =
                    os[tid*4] + os[tid*4+1] + os[tid*4+2] + os[tid*4+3] + fc2b[0];
            }
        }
        __syncthreads();
    }
}

// ---------------- launch -----------------------------------------------------
extern "C" void kernel_launch(void* const* d_in, const int* in_sizes, int n_in,
                              void* d_out, int out_size)
{
    (void)in_sizes; (void)n_in; (void)out_size;
    const float* f1     = (const float*)d_in[0];
    const float* f2     = (const float*)d_in[1];
    const float* enc1_w = (const float*)d_in[2];
    const float* enc1_b = (const float*)d_in[3];
    const float* enc2_w = (const float*)d_in[4];
    const float* enc2_b = (const float*)d_in[5];
    const float* affa_w = (const float*)d_in[6];
    const float* affv_w = (const float*)d_in[7];
    const float* wa_w   = (const float*)d_in[8];
    const float* wv_w   = (const float*)d_in[9];
    const float* wca_w  = (const float*)d_in[10];
    const float* wcv_w  = (const float*)d_in[11];
    const float* wha_w  = (const float*)d_in[12];
    const float* whv_w  = (const float*)d_in[13];
    const float* fc1_w  = (const float*)d_in[14];
    const float* fc1_b  = (const float*)d_in[15];
    const float* fc2_w  = (const float*)d_in[16];
    const float* fc2_b  = (const float*)d_in[17];
    float* out = (float*)d_out;

    cudaFuncSetAttribute(mma_fused, cudaFuncAttributeMaxDynamicSharedMemorySize, S_TOTAL);

    split_kernel<<<dim3(6, 16), 512>>>(wca_w, wcv_w, wha_w, whv_w, fc1_w);
    pre_enc_kernel<<<dim3(8, 4, 2), 256>>>(f1, f2, enc1_w, enc1_b, enc2_w, enc2_b);
    pre_aff_kernel<<<dim3(8, 4, 4), 256>>>(affa_w, affv_w, wa_w, wv_w);
    mma_fused<<<dim3(4, 256), 256, S_TOTAL>>>(fc1_b, fc2_w, fc2_b, out);
}

// round 14
// speedup vs baseline: 2.4173x; 1.0004x over previous
#include <cuda_runtime.h>
#include <cuda_fp16.h>
#include <cstdint>
#include <math.h>

#define ATT_SCALE 0.0625f
typedef uint32_t u32;

// ---------------- SMEM byte offsets ------------------------------------------
#define S_AHI   0                  // 64 x 264 fp16
#define S_ALO   33792
#define S_PARK  67584              // 64 x 260 fp32
#define S_AFF   134144             // 256 fp32
#define S_F1B   135168
#define S_F2W   136192
#define S_OSUM  137216             // 64 x 4 fp32
#define S_TOTAL 138240
#define A_STR   264                // fp16 per A row (pad: conflict-free ldmatrix)

// ---------------- device scratch ---------------------------------------------
__device__ float g_enc1[65536], g_enc2[65536];
__device__ float g_affa[65536], g_affv[65536];
__device__ float g_Xa[65536],   g_Xv[65536];
// 6 weights x 16 chunks x 16 colgroups x 32 uint4 (fp16, fragment order)
__device__ uint4 g_wfrag[6 * 8192];

// ---------------- small helpers ----------------------------------------------
__device__ __forceinline__ u32 smem_u32(const void* p) {
    u32 a;
    asm("{ .reg .u64 t; cvta.to.shared.u64 t, %1; cvt.u32.u64 %0, t; }" : "=r"(a) : "l"(p));
    return a;
}
__device__ __forceinline__ void ldsm4(u32 addr, u32* d) {
    asm volatile("ldmatrix.sync.aligned.m8n8.x4.shared.b16 {%0,%1,%2,%3}, [%4];"
        : "=r"(d[0]), "=r"(d[1]), "=r"(d[2]), "=r"(d[3]) : "r"(addr));
}
__device__ __forceinline__ void mma_f16(float* c, const u32* a, const u32* b) {
    asm volatile("mma.sync.aligned.m16n8k16.row.col.f32.f16.f16.f32 "
        "{%0,%1,%2,%3}, {%4,%5,%6,%7}, {%8,%9}, {%0,%1,%2,%3};"
        : "+f"(c[0]), "+f"(c[1]), "+f"(c[2]), "+f"(c[3])
        : "r"(a[0]), "r"(a[1]), "r"(a[2]), "r"(a[3]), "r"(b[0]), "r"(b[1]));
}
// fp16 hi/lo split of a float pair
__device__ __forceinline__ void split2(float v0, float v1, u32& rh, u32& rl) {
    __half h0 = __float2half(v0), h1 = __float2half(v1);
    __half l0 = __float2half(v0 - __half2float(h0));
    __half l1 = __float2half(v1 - __half2float(h1));
    rh = (u32)__half_as_ushort(h0) | ((u32)__half_as_ushort(h1) << 16);
    rl = (u32)__half_as_ushort(l0) | ((u32)__half_as_ushort(l1) << 16);
}
// fp16 round (hi only) of a float pair
__device__ __forceinline__ u32 pack2(float v0, float v1) {
    __half h0 = __float2half(v0), h1 = __float2half(v1);
    return (u32)__half_as_ushort(h0) | ((u32)__half_as_ushort(h1) << 16);
}
__device__ __forceinline__ float ftanh(float x) {
    float t = __expf(fminf(2.0f * x, 80.0f));
    return __fdividef(t - 1.0f, t + 1.0f);
}

// ---------------- prep GEMMs (SIMT fp32, known-correct) -----------------------
__device__ __forceinline__ void small_gemm(const float* __restrict__ A,
                                           const float* __restrict__ W,
                                           const float* __restrict__ bias,
                                           float* __restrict__ C, int K)
{
    __shared__ float As[32][17];
    __shared__ float Ws[64][17];
    const int i0 = blockIdx.x * 32, j0 = blockIdx.y * 64;
    const int tid = threadIdx.x;
    const int tx = tid & 15, ty = tid >> 4;
    const int ar = tid >> 2, ak = (tid & 3) * 4;
    float acc[2][4] = {};
    for (int k0 = 0; k0 < K; k0 += 16) {
        float4 av = make_float4(0.f, 0.f, 0.f, 0.f);
        if (tid < 128) av = *(const float4*)(A + (size_t)(i0 + ar) * K + k0 + ak);
        float4 wv = *(const float4*)(W + (size_t)(j0 + ar) * K + k0 + ak);
        __syncthreads();
        if (tid < 128) {
            As[ar][ak] = av.x; As[ar][ak+1] = av.y; As[ar][ak+2] = av.z; As[ar][ak+3] = av.w;
        }
        Ws[ar][ak] = wv.x; Ws[ar][ak+1] = wv.y; Ws[ar][ak+2] = wv.z; Ws[ar][ak+3] = wv.w;
        __syncthreads();
        #pragma unroll
        for (int kk = 0; kk < 16; kk++) {
            float a0 = As[ty*2][kk], a1 = As[ty*2+1][kk];
            float b0 = Ws[tx*4][kk], b1 = Ws[tx*4+1][kk];
            float b2 = Ws[tx*4+2][kk], b3 = Ws[tx*4+3][kk];
            acc[0][0] = fmaf(a0,b0,acc[0][0]); acc[0][1] = fmaf(a0,b1,acc[0][1]);
            acc[0][2] = fmaf(a0,b2,acc[0][2]); acc[0][3] = fmaf(a0,b3,acc[0][3]);
            acc[1][0] = fmaf(a1,b0,acc[1][0]); acc[1][1] = fmaf(a1,b1,acc[1][1]);
            acc[1][2] = fmaf(a1,b2,acc[1][2]); acc[1][3] = fmaf(a1,b3,acc[1][3]);
        }
    }
    #pragma unroll
    for (int u = 0; u < 2; u++)
        #pragma unroll
        for (int v = 0; v < 4; v++) {
            int j = j0 + tx*4 + v;
            float x = acc[u][v];
            if (bias) x += bias[j];
            C[(size_t)(i0 + ty*2 + u) * 256 + j] = x;
        }
}

__global__ void pre_enc_kernel(const float* __restrict__ f1, const float* __restrict__ f2,
                               const float* __restrict__ w1, const float* __restrict__ b1,
                               const float* __restrict__ w2, const float* __restrict__ b2)
{
    if (blockIdx.z == 0) small_gemm(f1, w1, b1, g_enc1, 768);
    else                 small_gemm(f2, w2, b2, g_enc2, 768);
}

__global__ void pre_aff_kernel(const float* __restrict__ affa, const float* __restrict__ affv,
                               const float* __restrict__ wa,   const float* __restrict__ wv)
{
    int z = blockIdx.z;
    const float* A = (z == 0 || z == 2) ? g_enc1 : g_enc2;
    const float* W = (z == 0) ? affa : (z == 1) ? affv : (z == 2) ? wa : wv;
    float*       C = (z == 0) ? g_affa : (z == 1) ? g_affv : (z == 2) ? g_Xa : g_Xv;
    small_gemm(A, W, nullptr, C, 256);
}

// ---------------- weight split: fp32 -> fp16 FRAGMENT layout ------------------
// For (w, chunk c, colgroup jc): 512B block. Lane l's uint4 = mma B frag
// th[0..3]: {n=jc*16+l/4, k=c*16+(l%4)*2}, {n, k+8}, {n+8, k}, {n+8, k+8}.
__global__ void split_kernel(const float* __restrict__ wca, const float* __restrict__ wcv,
                             const float* __restrict__ wha, const float* __restrict__ whv,
                             const float* __restrict__ fc1w)
{
    int w = blockIdx.x, c = blockIdx.y;
    int jc = threadIdx.x >> 5, lane = threadIdx.x & 31;
    const float* src; int stride = 256, co = 0;
    switch (w) {
        case 0: src = wca; break;
        case 1: src = wha; break;
        case 2: src = fc1w; stride = 512; break;
        case 3: src = wcv; break;
        case 4: src = whv; break;
        default: src = fc1w; stride = 512; co = 256; break;
    }
    int n0 = jc * 16 + (lane >> 2);
    int k0 = c * 16 + (lane & 3) * 2;
    const float* r0 = src + (size_t)n0 * stride + co;
    const float* r1 = src + (size_t)(n0 + 8) * stride + co;
    uint4 hv;
    hv.x = pack2(r0[k0],     r0[k0 + 1]);
    hv.y = pack2(r0[k0 + 8], r0[k0 + 9]);
    hv.z = pack2(r1[k0],     r1[k0 + 1]);
    hv.w = pack2(r1[k0 + 8], r1[k0 + 9]);
    g_wfrag[((size_t)(w * 16 + c) * 16 + jc) * 32 + lane] = hv;
}

// ---------------- tensor-core mainloop ---------------------------------------
__device__ __forceinline__ void lda(u32 sb, int arow, int akof, u32 ah[2][4], u32 al[2][4]) {
    #pragma unroll
    for (int mt = 0; mt < 2; mt++) {
        u32 ao = sb + S_AHI + (u32)(((arow + mt*16) * A_STR + akof) * 2);
        ldsm4(ao, ah[mt]);
        ldsm4(ao + (S_ALO - S_AHI), al[mt]);
    }
}
// 2-pass fp16: D = Ahi*B + Alo*B. Pass-outermost: 16 independent HMMAs between
// revisits of any accumulator quad.
__device__ __forceinline__ void mma_group(float acc[2][8][4], u32 ah[2][4], u32 al[2][4],
                                          uint4 bh[4]) {
    #pragma unroll
    for (int np = 0; np < 4; np++) {
        const u32* th = (const u32*)&bh[np];
        #pragma unroll
        for (int mt = 0; mt < 2; mt++) {
            mma_f16(acc[mt][np*2],   ah[mt], th);
            mma_f16(acc[mt][np*2+1], ah[mt], th + 2);
        }
    }
    #pragma unroll
    for (int np = 0; np < 4; np++) {
        const u32* th = (const u32*)&bh[np];
        #pragma unroll
        for (int mt = 0; mt < 2; mt++) {
            mma_f16(acc[mt][np*2],   al[mt], th);
            mma_f16(acc[mt][np*2+1], al[mt], th + 2);
        }
    }
}
#define LOADB(bh, cc) do { \
    _Pragma("unroll") \
    for (int np = 0; np < 4; np++) { \
        bh[np] = __ldg(wf + ((size_t)(cc) * 16 + cg4 + np) * 32 + lane); \
    } \
} while (0)

// C tile: rows [r0,+32) of the CTA's 64, cols [cg*64,+64). No barriers inside
// the k-loop. Both B (GMEM) and A (SMEM ldmatrix) are software-pipelined one
// chunk ahead so HMMA latency covers the loads.
__device__ __forceinline__ void run_gemm(const uint4* __restrict__ wf, u32 sb,
                                         int lane, int r0, int cg, float acc[2][8][4])
{
    #pragma unroll
    for (int mt = 0; mt < 2; mt++)
        #pragma unroll
        for (int nt = 0; nt < 8; nt++)
            #pragma unroll
            for (int q = 0; q < 4; q++) acc[mt][nt][q] = 0.f;

    __syncthreads();                       // A writes (attn/epilogue) visible
    const int g = lane >> 3, r = lane & 7;
    const int arow = r0 + (g & 1)*8 + r;
    const int akb  = (g >> 1)*8;
    const int cg4  = cg * 4;

    uint4 b0h[4], b1h[4];
    u32 ah0[2][4], al0[2][4], ah1[2][4], al1[2][4];
    LOADB(b0h, 0);
    lda(sb, arow, akb, ah0, al0);
    #pragma unroll
    for (int c = 0; c < 16; c += 2) {
        LOADB(b1h, c + 1);
        lda(sb, arow, (c+1)*16 + akb, ah1, al1);
        mma_group(acc, ah0, al0, b0h);
        if (c + 2 < 16) {
            LOADB(b0h, c + 2);
            lda(sb, arow, (c+2)*16 + akb, ah0, al0);
        }
        mma_group(acc, ah1, al1, b1h);
    }
    __syncthreads();                       // all reads of A done before rewrite
}

// ---------------- fused kernel -----------------------------------------------
__global__ void __launch_bounds__(256, 1)
mma_fused(const float* __restrict__ fc1b, const float* __restrict__ fc2w,
          const float* __restrict__ fc2b, float* __restrict__ out)
{
    extern __shared__ char sm[];
    u32 sb = smem_u32(sm);
    const int tid = threadIdx.x, lane = tid & 31, w = tid >> 5;
    const int b = blockIdx.y, i0 = blockIdx.x * 64;
    const int r0 = (w & 1) * 32, cg = w >> 1, c0 = cg * 64;
    const int qr = lane >> 2, qc = (lane & 3) * 2;

    ((float*)(sm + S_F1B))[tid] = fc1b[tid];
    ((float*)(sm + S_F2W))[tid] = fc2w[tid];

    float acc[2][8][4];

    for (int br = 0; br < 2; br++) {
        const float* genc = br ? g_enc2 : g_enc1;
        const float* gaff = br ? g_affv : g_affa;
        const float* gX   = br ? g_Xv   : g_Xa;
        const uint4* wb   = g_wfrag + (size_t)(br * 3) * 8192;

        __syncthreads();
        ((float*)(sm + S_AFF))[tid] = gaff[b*256 + tid];
        __syncthreads();

        // ---- attn tile -> A hi/lo (rank-1 outer product) ----
        {
            int row = tid >> 2, cb = (tid & 3) * 64;
            float ev = genc[b*256 + i0 + row] * ATT_SCALE;
            const float* aff = (const float*)(sm + S_AFF);
            #pragma unroll 4
            for (int p = 0; p < 32; p++) {
                int col = cb + 2*p;
                float v0 = ftanh(ev * aff[col]), v1 = ftanh(ev * aff[col + 1]);
                u32 rh, rl; split2(v0, v1, rh, rl);
                u32 off = (u32)((row * A_STR + col) * 2);
                *(u32*)(sm + S_AHI + off) = rh;
                *(u32*)(sm + S_ALO + off) = rl;
            }
        }

        // ---- GEMM1: D = attn @ Wc^T ; A = relu(D + X) ----
        run_gemm(wb, sb, lane, r0, cg, acc);
        #pragma unroll
        for (int mt = 0; mt < 2; mt++)
            #pragma unroll
            for (int rs = 0; rs < 2; rs++) {
                int row = r0 + mt*16 + rs*8 + qr;
                #pragma unroll
                for (int nt = 0; nt < 8; nt++) {
                    int col = c0 + nt*8 + qc;
                    float2 xv = *(const float2*)(gX + (size_t)(i0 + row)*256 + col);
                    float v0 = fmaxf(acc[mt][nt][rs*2]   + xv.x, 0.f);
                    float v1 = fmaxf(acc[mt][nt][rs*2+1] + xv.y, 0.f);
                    u32 rh, rl; split2(v0, v1, rh, rl);
                    u32 off = (u32)((row * A_STR + col) * 2);
                    *(u32*)(sm + S_AHI + off) = rh;
                    *(u32*)(sm + S_ALO + off) = rl;
                }
            }

        // ---- GEMM2: D = H @ Wh^T ; A = D + enc ----
        run_gemm(wb + 8192, sb, lane, r0, cg, acc);
        #pragma unroll
        for (int mt = 0; mt < 2; mt++)
            #pragma unroll
            for (int rs = 0; rs < 2; rs++) {
                int row = r0 + mt*16 + rs*8 + qr;
                #pragma unroll
                for (int nt = 0; nt < 8; nt++) {
                    int col = c0 + nt*8 + qc;
                    float2 ev2 = *(const float2*)(genc + (size_t)(i0 + row)*256 + col);
                    float v0 = acc[mt][nt][rs*2]   + ev2.x;
                    float v1 = acc[mt][nt][rs*2+1] + ev2.y;
                    u32 rh, rl; split2(v0, v1, rh, rl);
                    u32 off = (u32)((row * A_STR + col) * 2);
                    *(u32*)(sm + S_AHI + off) = rh;
                    *(u32*)(sm + S_ALO + off) = rl;
                }
            }

        // ---- GEMM3: D = attn_enc @ fc1_half^T ----
        run_gemm(wb + 16384, sb, lane, r0, cg, acc);
        if (br == 0) {
            #pragma unroll
            for (int mt = 0; mt < 2; mt++)
                #pragma unroll
                for (int rs = 0; rs < 2; rs++) {
                    int row = r0 + mt*16 + rs*8 + qr;
                    #pragma unroll
                    for (int nt = 0; nt < 8; nt++) {
                        int col = c0 + nt*8 + qc;
                        *(float2*)(sm + S_PARK + (u32)((row*260 + col) * 4)) =
                            make_float2(acc[mt][nt][rs*2], acc[mt][nt][rs*2+1]);
                    }
                }
        } else {
            const float* f1bs = (const float*)(sm + S_F1B);
            const float* f2ws = (const float*)(sm + S_F2W);
            #pragma unroll
            for (int mt = 0; mt < 2; mt++)
                #pragma unroll
                for (int rs = 0; rs < 2; rs++) {
                    int row = r0 + mt*16 + rs*8 + qr;
                    float s = 0.f;
                    #pragma unroll
                    for (int nt = 0; nt < 8; nt++) {
                        int col = c0 + nt*8 + qc;
                        float2 pk = *(const float2*)(sm + S_PARK + (u32)((row*260 + col) * 4));
                        float h0 = fmaxf(acc[mt][nt][rs*2]   + pk.x + f1bs[col],     0.f);
                        float h1 = fmaxf(acc[mt][nt][rs*2+1] + pk.y + f1bs[col + 1], 0.f);
                        s = fmaf(h0, f2ws[col], s);
                        s = fmaf(h1, f2ws[col + 1], s);
                    }
                    s += __shfl_xor_sync(0xffffffffu, s, 1);
                    s += __shfl_xor_sync(0xffffffffu, s, 2);
                    if ((lane & 3) == 0)
                        ((float*)(sm + S_OSUM))[row*4 + cg] = s;
                }
            __syncthreads();
            if (tid < 64) {
                const float* os = (const float*)(sm + S_OSUM);
                out[b*256 + i0 + tid] =
                    os[tid*4] + os[tid*4+1] + os[tid*4+2] + os[tid*4+3] + fc2b[0];
            }
        }
        __syncthreads();
    }
}

// ---------------- launch -----------------------------------------------------
extern "C" void kernel_launch(void* const* d_in, const int* in_sizes, int n_in,
                              void* d_out, int out_size)
{
    (void)in_sizes; (void)n_in; (void)out_size;
    const float* f1     = (const float*)d_in[0];
    const float* f2     = (const float*)d_in[1];
    const float* enc1_w = (const float*)d_in[2];
    const float* enc1_b = (const float*)d_in[3];
    const float* enc2_w = (const float*)d_in[4];
    const float* enc2_b = (const float*)d_in[5];
    const float* affa_w = (const float*)d_in[6];
    const float* affv_w = (const float*)d_in[7];
    const float* wa_w   = (const float*)d_in[8];
    const float* wv_w   = (const float*)d_in[9];
    const float* wca_w  = (const float*)d_in[10];
    const float* wcv_w  = (const float*)d_in[11];
    const float* wha_w  = (const float*)d_in[12];
    const float* whv_w  = (const float*)d_in[13];
    const float* fc1_w  = (const float*)d_in[14];
    const float* fc1_b  = (const float*)d_in[15];
    const float* fc2_w  = (const float*)d_in[16];
    const float* fc2_b  = (const float*)d_in[17];
    float* out = (float*)d_out;

    cudaFuncSetAttribute(mma_fused, cudaFuncAttributeMaxDynamicSharedMemorySize, S_TOTAL);

    split_kernel<<<dim3(6, 16), 512>>>(wca_w, wcv_w, wha_w, whv_w, fc1_w);
    pre_enc_kernel<<<dim3(8, 4, 2), 256>>>(f1, f2, enc1_w, enc1_b, enc2_w, enc2_b);
    pre_aff_kernel<<<dim3(8, 4, 4), 256>>>(affa_w, affv_w, wa_w, wv_w);
    mma_fused<<<dim3(4, 256), 256, S_TOTAL>>>(fc1_b, fc2_w, fc2_b, out);
}

// round 15
// speedup vs baseline: 3.4590x; 1.4309x over previous
#include <cuda_runtime.h>
#include <cuda_fp16.h>
#include <cstdint>
#include <math.h>

#define ATT_SCALE 0.0625f
typedef uint32_t u32;

// ---------------- SMEM byte offsets ------------------------------------------
#define S_AHI   0                  // 64 x 264 fp16
#define S_PARK  33792              // 64 x 260 fp32
#define S_AFF   100352             // 256 fp32
#define S_F1B   101376
#define S_F2W   102400
#define S_OSUM  103424             // 64 x 4 fp32
#define S_TOTAL 104448
#define A_STR   264                // fp16 per A row (pad: conflict-free ldmatrix)

// ---------------- device scratch ---------------------------------------------
__device__ float g_enc1[65536], g_enc2[65536];
__device__ float g_affa[65536], g_affv[65536];
__device__ float g_Xa[65536],   g_Xv[65536];
// 6 weights x 16 chunks x 16 colgroups x 32 uint4 (fp16, fragment order)
__device__ uint4 g_wfrag[6 * 8192];

// ---------------- small helpers ----------------------------------------------
__device__ __forceinline__ u32 smem_u32(const void* p) {
    u32 a;
    asm("{ .reg .u64 t; cvta.to.shared.u64 t, %1; cvt.u32.u64 %0, t; }" : "=r"(a) : "l"(p));
    return a;
}
__device__ __forceinline__ void ldsm4(u32 addr, u32* d) {
    asm volatile("ldmatrix.sync.aligned.m8n8.x4.shared.b16 {%0,%1,%2,%3}, [%4];"
        : "=r"(d[0]), "=r"(d[1]), "=r"(d[2]), "=r"(d[3]) : "r"(addr));
}
__device__ __forceinline__ void mma_f16(float* c, const u32* a, const u32* b) {
    asm volatile("mma.sync.aligned.m16n8k16.row.col.f32.f16.f16.f32 "
        "{%0,%1,%2,%3}, {%4,%5,%6,%7}, {%8,%9}, {%0,%1,%2,%3};"
        : "+f"(c[0]), "+f"(c[1]), "+f"(c[2]), "+f"(c[3])
        : "r"(a[0]), "r"(a[1]), "r"(a[2]), "r"(a[3]), "r"(b[0]), "r"(b[1]));
}
// fp16 round of a float pair
__device__ __forceinline__ u32 pack2(float v0, float v1) {
    __half h0 = __float2half(v0), h1 = __float2half(v1);
    return (u32)__half_as_ushort(h0) | ((u32)__half_as_ushort(h1) << 16);
}
__device__ __forceinline__ float ftanh(float x) {
    float t = __expf(fminf(2.0f * x, 80.0f));
    return __fdividef(t - 1.0f, t + 1.0f);
}

// ---------------- prep GEMMs (SIMT fp32, known-correct) -----------------------
__device__ __forceinline__ void small_gemm(const float* __restrict__ A,
                                           const float* __restrict__ W,
                                           const float* __restrict__ bias,
                                           float* __restrict__ C, int K)
{
    __shared__ float As[32][17];
    __shared__ float Ws[64][17];
    const int i0 = blockIdx.x * 32, j0 = blockIdx.y * 64;
    const int tid = threadIdx.x;
    const int tx = tid & 15, ty = tid >> 4;
    const int ar = tid >> 2, ak = (tid & 3) * 4;
    float acc[2][4] = {};
    for (int k0 = 0; k0 < K; k0 += 16) {
        float4 av = make_float4(0.f, 0.f, 0.f, 0.f);
        if (tid < 128) av = *(const float4*)(A + (size_t)(i0 + ar) * K + k0 + ak);
        float4 wv = *(const float4*)(W + (size_t)(j0 + ar) * K + k0 + ak);
        __syncthreads();
        if (tid < 128) {
            As[ar][ak] = av.x; As[ar][ak+1] = av.y; As[ar][ak+2] = av.z; As[ar][ak+3] = av.w;
        }
        Ws[ar][ak] = wv.x; Ws[ar][ak+1] = wv.y; Ws[ar][ak+2] = wv.z; Ws[ar][ak+3] = wv.w;
        __syncthreads();
        #pragma unroll
        for (int kk = 0; kk < 16; kk++) {
            float a0 = As[ty*2][kk], a1 = As[ty*2+1][kk];
            float b0 = Ws[tx*4][kk], b1 = Ws[tx*4+1][kk];
            float b2 = Ws[tx*4+2][kk], b3 = Ws[tx*4+3][kk];
            acc[0][0] = fmaf(a0,b0,acc[0][0]); acc[0][1] = fmaf(a0,b1,acc[0][1]);
            acc[0][2] = fmaf(a0,b2,acc[0][2]); acc[0][3] = fmaf(a0,b3,acc[0][3]);
            acc[1][0] = fmaf(a1,b0,acc[1][0]); acc[1][1] = fmaf(a1,b1,acc[1][1]);
            acc[1][2] = fmaf(a1,b2,acc[1][2]); acc[1][3] = fmaf(a1,b3,acc[1][3]);
        }
    }
    #pragma unroll
    for (int u = 0; u < 2; u++)
        #pragma unroll
        for (int v = 0; v < 4; v++) {
            int j = j0 + tx*4 + v;
            float x = acc[u][v];
            if (bias) x += bias[j];
            C[(size_t)(i0 + ty*2 + u) * 256 + j] = x;
        }
}

__global__ void pre_enc_kernel(const float* __restrict__ f1, const float* __restrict__ f2,
                               const float* __restrict__ w1, const float* __restrict__ b1,
                               const float* __restrict__ w2, const float* __restrict__ b2)
{
    if (blockIdx.z == 0) small_gemm(f1, w1, b1, g_enc1, 768);
    else                 small_gemm(f2, w2, b2, g_enc2, 768);
}

__global__ void pre_aff_kernel(const float* __restrict__ affa, const float* __restrict__ affv,
                               const float* __restrict__ wa,   const float* __restrict__ wv)
{
    int z = blockIdx.z;
    const float* A = (z == 0 || z == 2) ? g_enc1 : g_enc2;
    const float* W = (z == 0) ? affa : (z == 1) ? affv : (z == 2) ? wa : wv;
    float*       C = (z == 0) ? g_affa : (z == 1) ? g_affv : (z == 2) ? g_Xa : g_Xv;
    small_gemm(A, W, nullptr, C, 256);
}

// ---------------- weight split: fp32 -> fp16 FRAGMENT layout ------------------
// For (w, chunk c, colgroup jc): 512B block. Lane l's uint4 = mma B frag
// th[0..3]: {n=jc*16+l/4, k=c*16+(l%4)*2}, {n, k+8}, {n+8, k}, {n+8, k+8}.
__global__ void split_kernel(const float* __restrict__ wca, const float* __restrict__ wcv,
                             const float* __restrict__ wha, const float* __restrict__ whv,
                             const float* __restrict__ fc1w)
{
    int w = blockIdx.x, c = blockIdx.y;
    int jc = threadIdx.x >> 5, lane = threadIdx.x & 31;
    const float* src; int stride = 256, co = 0;
    switch (w) {
        case 0: src = wca; break;
        case 1: src = wha; break;
        case 2: src = fc1w; stride = 512; break;
        case 3: src = wcv; break;
        case 4: src = whv; break;
        default: src = fc1w; stride = 512; co = 256; break;
    }
    int n0 = jc * 16 + (lane >> 2);
    int k0 = c * 16 + (lane & 3) * 2;
    const float* r0 = src + (size_t)n0 * stride + co;
    const float* r1 = src + (size_t)(n0 + 8) * stride + co;
    uint4 hv;
    hv.x = pack2(r0[k0],     r0[k0 + 1]);
    hv.y = pack2(r0[k0 + 8], r0[k0 + 9]);
    hv.z = pack2(r1[k0],     r1[k0 + 1]);
    hv.w = pack2(r1[k0 + 8], r1[k0 + 9]);
    g_wfrag[((size_t)(w * 16 + c) * 16 + jc) * 32 + lane] = hv;
}

// ---------------- tensor-core mainloop ---------------------------------------
__device__ __forceinline__ void lda(u32 sb, int arow, int akof, u32 ah[2][4]) {
    #pragma unroll
    for (int mt = 0; mt < 2; mt++) {
        u32 ao = sb + S_AHI + (u32)(((arow + mt*16) * A_STR + akof) * 2);
        ldsm4(ao, ah[mt]);
    }
}
// 1-pass fp16: D = A*B. 8 HMMAs per chunk, each acc quad touched once.
__device__ __forceinline__ void mma_group(float acc[2][8][4], u32 ah[2][4], uint4 bh[4]) {
    #pragma unroll
    for (int np = 0; np < 4; np++) {
        const u32* th = (const u32*)&bh[np];
        #pragma unroll
        for (int mt = 0; mt < 2; mt++) {
            mma_f16(acc[mt][np*2],   ah[mt], th);
            mma_f16(acc[mt][np*2+1], ah[mt], th + 2);
        }
    }
}
#define LOADB(bh, cc) do { \
    _Pragma("unroll") \
    for (int np = 0; np < 4; np++) { \
        bh[np] = __ldg(wf + ((size_t)(cc) * 16 + cg4 + np) * 32 + lane); \
    } \
} while (0)

// C tile: rows [r0,+32) of the CTA's 64, cols [cg*64,+64). No barriers inside
// the k-loop. Both B (GMEM) and A (SMEM ldmatrix) pipelined one chunk ahead.
__device__ __forceinline__ void run_gemm(const uint4* __restrict__ wf, u32 sb,
                                         int lane, int r0, int cg, float acc[2][8][4])
{
    #pragma unroll
    for (int mt = 0; mt < 2; mt++)
        #pragma unroll
        for (int nt = 0; nt < 8; nt++)
            #pragma unroll
            for (int q = 0; q < 4; q++) acc[mt][nt][q] = 0.f;

    __syncthreads();                       // A writes (attn/epilogue) visible
    const int g = lane >> 3, r = lane & 7;
    const int arow = r0 + (g & 1)*8 + r;
    const int akb  = (g >> 1)*8;
    const int cg4  = cg * 4;

    uint4 b0h[4], b1h[4];
    u32 ah0[2][4], ah1[2][4];
    LOADB(b0h, 0);
    lda(sb, arow, akb, ah0);
    #pragma unroll
    for (int c = 0; c < 16; c += 2) {
        LOADB(b1h, c + 1);
        lda(sb, arow, (c+1)*16 + akb, ah1);
        mma_group(acc, ah0, b0h);
        if (c + 2 < 16) {
            LOADB(b0h, c + 2);
            lda(sb, arow, (c+2)*16 + akb, ah0);
        }
        mma_group(acc, ah1, b1h);
    }
    __syncthreads();                       // all reads of A done before rewrite
}

// ---------------- fused kernel -----------------------------------------------
__global__ void __launch_bounds__(256, 1)
mma_fused(const float* __restrict__ fc1b, const float* __restrict__ fc2w,
          const float* __restrict__ fc2b, float* __restrict__ out)
{
    extern __shared__ char sm[];
    u32 sb = smem_u32(sm);
    const int tid = threadIdx.x, lane = tid & 31, w = tid >> 5;
    const int b = blockIdx.y, i0 = blockIdx.x * 64;
    const int r0 = (w & 1) * 32, cg = w >> 1, c0 = cg * 64;
    const int qr = lane >> 2, qc = (lane & 3) * 2;

    ((float*)(sm + S_F1B))[tid] = fc1b[tid];
    ((float*)(sm + S_F2W))[tid] = fc2w[tid];

    float acc[2][8][4];

    for (int br = 0; br < 2; br++) {
        const float* genc = br ? g_enc2 : g_enc1;
        const float* gaff = br ? g_affv : g_affa;
        const float* gX   = br ? g_Xv   : g_Xa;
        const uint4* wb   = g_wfrag + (size_t)(br * 3) * 8192;

        __syncthreads();
        ((float*)(sm + S_AFF))[tid] = gaff[b*256 + tid];
        __syncthreads();

        // ---- attn tile -> A fp16 (rank-1 outer product) ----
        {
            int row = tid >> 2, cb = (tid & 3) * 64;
            float ev = genc[b*256 + i0 + row] * ATT_SCALE;
            const float* aff = (const float*)(sm + S_AFF);
            #pragma unroll 4
            for (int p = 0; p < 32; p++) {
                int col = cb + 2*p;
                float v0 = ftanh(ev * aff[col]), v1 = ftanh(ev * aff[col + 1]);
                *(u32*)(sm + S_AHI + (u32)((row * A_STR + col) * 2)) = pack2(v0, v1);
            }
        }

        // ---- GEMM1: D = attn @ Wc^T ; A = relu(D + X) ----
        run_gemm(wb, sb, lane, r0, cg, acc);
        #pragma unroll
        for (int mt = 0; mt < 2; mt++)
            #pragma unroll
            for (int rs = 0; rs < 2; rs++) {
                int row = r0 + mt*16 + rs*8 + qr;
                #pragma unroll
                for (int nt = 0; nt < 8; nt++) {
                    int col = c0 + nt*8 + qc;
                    float2 xv = *(const float2*)(gX + (size_t)(i0 + row)*256 + col);
                    float v0 = fmaxf(acc[mt][nt][rs*2]   + xv.x, 0.f);
                    float v1 = fmaxf(acc[mt][nt][rs*2+1] + xv.y, 0.f);
                    *(u32*)(sm + S_AHI + (u32)((row * A_STR + col) * 2)) = pack2(v0, v1);
                }
            }

        // ---- GEMM2: D = H @ Wh^T ; A = D + enc ----
        run_gemm(wb + 8192, sb, lane, r0, cg, acc);
        #pragma unroll
        for (int mt = 0; mt < 2; mt++)
            #pragma unroll
            for (int rs = 0; rs < 2; rs++) {
                int row = r0 + mt*16 + rs*8 + qr;
                #pragma unroll
                for (int nt = 0; nt < 8; nt++) {
                    int col = c0 + nt*8 + qc;
                    float2 ev2 = *(const float2*)(genc + (size_t)(i0 + row)*256 + col);
                    float v0 = acc[mt][nt][rs*2]   + ev2.x;
                    float v1 = acc[mt][nt][rs*2+1] + ev2.y;
                    *(u32*)(sm + S_AHI + (u32)((row * A_STR + col) * 2)) = pack2(v0, v1);
                }
            }

        // ---- GEMM3: D = attn_enc @ fc1_half^T ----
        run_gemm(wb + 16384, sb, lane, r0, cg, acc);
        if (br == 0) {
            #pragma unroll
            for (int mt = 0; mt < 2; mt++)
                #pragma unroll
                for (int rs = 0; rs < 2; rs++) {
                    int row = r0 + mt*16 + rs*8 + qr;
                    #pragma unroll
                    for (int nt = 0; nt < 8; nt++) {
                        int col = c0 + nt*8 + qc;
                        *(float2*)(sm + S_PARK + (u32)((row*260 + col) * 4)) =
                            make_float2(acc[mt][nt][rs*2], acc[mt][nt][rs*2+1]);
                    }
                }
        } else {
            const float* f1bs = (const float*)(sm + S_F1B);
            const float* f2ws = (const float*)(sm + S_F2W);
            #pragma unroll
            for (int mt = 0; mt < 2; mt++)
                #pragma unroll
                for (int rs = 0; rs < 2; rs++) {
                    int row = r0 + mt*16 + rs*8 + qr;
                    float s = 0.f;
                    #pragma unroll
                    for (int nt = 0; nt < 8; nt++) {
                        int col = c0 + nt*8 + qc;
                        float2 pk = *(const float2*)(sm + S_PARK + (u32)((row*260 + col) * 4));
                        float h0 = fmaxf(acc[mt][nt][rs*2]   + pk.x + f1bs[col],     0.f);
                        float h1 = fmaxf(acc[mt][nt][rs*2+1] + pk.y + f1bs[col + 1], 0.f);
                        s = fmaf(h0, f2ws[col], s);
                        s = fmaf(h1, f2ws[col + 1], s);
                    }
                    s += __shfl_xor_sync(0xffffffffu, s, 1);
                    s += __shfl_xor_sync(0xffffffffu, s, 2);
                    if ((lane & 3) == 0)
                        ((float*)(sm + S_OSUM))[row*4 + cg] = s;
                }
            __syncthreads();
            if (tid < 64) {
                const float* os = (const float*)(sm + S_OSUM);
                out[b*256 + i0 + tid] =
                    os[tid*4] + os[tid*4+1] + os[tid*4+2] + os[tid*4+3] + fc2b[0];
            }
        }
        __syncthreads();
    }
}

// ---------------- launch -----------------------------------------------------
extern "C" void kernel_launch(void* const* d_in, const int* in_sizes, int n_in,
                              void* d_out, int out_size)
{
    (void)in_sizes; (void)n_in; (void)out_size;
    const float* f1     = (const float*)d_in[0];
    const float* f2     = (const float*)d_in[1];
    const float* enc1_w = (const float*)d_in[2];
    const float* enc1_b = (const float*)d_in[3];
    const float* enc2_w = (const float*)d_in[4];
    const float* enc2_b = (const float*)d_in[5];
    const float* affa_w = (const float*)d_in[6];
    const float* affv_w = (const float*)d_in[7];
    const float* wa_w   = (const float*)d_in[8];
    const float* wv_w   = (const float*)d_in[9];
    const float* wca_w  = (const float*)d_in[10];
    const float* wcv_w  = (const float*)d_in[11];
    const float* wha_w  = (const float*)d_in[12];
    const float* whv_w  = (const float*)d_in[13];
    const float* fc1_w  = (const float*)d_in[14];
    const float* fc1_b  = (const float*)d_in[15];
    const float* fc2_w  = (const float*)d_in[16];
    const float* fc2_b  = (const float*)d_in[17];
    float* out = (float*)d_out;

    cudaFuncSetAttribute(mma_fused, cudaFuncAttributeMaxDynamicSharedMemorySize, S_TOTAL);

    split_kernel<<<dim3(6, 16), 512>>>(wca_w, wcv_w, wha_w, whv_w, fc1_w);
    pre_enc_kernel<<<dim3(8, 4, 2), 256>>>(f1, f2, enc1_w, enc1_b, enc2_w, enc2_b);
    pre_aff_kernel<<<dim3(8, 4, 4), 256>>>(affa_w, affv_w, wa_w, wv_w);
    mma_fused<<<dim3(4, 256), 256, S_TOTAL>>>(fc1_b, fc2_w, fc2_b, out);
}